// round 3
// baseline (speedup 1.0000x reference)
#include <cuda_runtime.h>
#include <cuda_fp16.h>
#include <cstdint>

// ============================================================================
// Problem constants
// ============================================================================
#define B_   4
#define C_   64
#define H_   128
#define W_   128
#define Q_   65536
// rows = 4 branches * B * Q = 1,048,576 ; 128 rows per CTA -> 8192 CTAs

// ============================================================================
// Device scratch (no cudaMalloc allowed)
// ============================================================================
__device__ __align__(16) __half g_featT[(size_t)B_ * H_ * W_ * C_]; // [B,H,W,C] fp16
__device__ __align__(16) __half g_w0i[256 * 128];  // [n=256][k=128] (real K=68)
__device__ __align__(16) __half g_w1i[256 * 256];  // [n][k]
__device__ __align__(16) __half g_w2i[256 * 256];
__device__ __align__(16) __half g_w3i[256 * 256];
__device__ __align__(16) __half g_w4i[8 * 256];    // [n=8][k=256] (real N=3)

// ============================================================================
// Prep kernels
// ============================================================================
__global__ void prep_feat(const float* __restrict__ feat) {
    int o = blockIdx.x * blockDim.x + threadIdx.x;
    if (o >= B_ * H_ * W_ * C_) return;
    int c  = o & 63;
    int ix = (o >> 6) & 127;
    int iy = (o >> 13) & 127;
    int b  = o >> 20;
    float v = feat[(((size_t)b * C_ + c) * H_ + iy) * W_ + ix];
    g_featT[o] = __float2half(v);
}

__global__ void prep_w(const float* __restrict__ w0, const float* __restrict__ w1,
                       const float* __restrict__ w2, const float* __restrict__ w3,
                       const float* __restrict__ w4) {
    int o = blockIdx.x * blockDim.x + threadIdx.x;
    if (o < 32768) {                        // W0: [256][128], real K=68
        int n = o >> 7, k = o & 127;
        g_w0i[o] = __float2half(k < 68 ? w0[k * 256 + n] : 0.0f);
    } else if (o < 32768 + 3 * 65536) {     // W1..W3: [256][256]
        int i = o - 32768;
        int l = i >> 16; i &= 65535;
        int n = i >> 8, k = i & 255;
        const float* w = (l == 0) ? w1 : ((l == 1) ? w2 : w3);
        __half* d = (l == 0) ? g_w1i : ((l == 1) ? g_w2i : g_w3i);
        d[i] = __float2half(w[k * 256 + n]);
    } else if (o < 32768 + 3 * 65536 + 2048) { // W4: [8][256], real N=3
        int i = o - 32768 - 3 * 65536;
        int n = i >> 8, k = i & 255;
        g_w4i[i] = __float2half(n < 3 ? w4[k * 3 + n] : 0.0f);
    }
}

// ============================================================================
// PTX wrappers (baseline PTX: sm_80-class, works at compute_103)
// ============================================================================
__device__ __forceinline__ uint32_t smem_u32(const void* p) {
    uint32_t a;
    asm("{ .reg .u64 t; cvta.to.shared.u64 t, %1; cvt.u32.u64 %0, t; }" : "=r"(a) : "l"(p));
    return a;
}
__device__ __forceinline__ void ldsm_x4(uint32_t* r, uint32_t addr) {
    asm volatile("ldmatrix.sync.aligned.m8n8.x4.shared.b16 {%0,%1,%2,%3}, [%4];"
                 : "=r"(r[0]), "=r"(r[1]), "=r"(r[2]), "=r"(r[3]) : "r"(addr));
}
__device__ __forceinline__ void ldsm_x2(uint32_t* r, uint32_t addr) {
    asm volatile("ldmatrix.sync.aligned.m8n8.x2.shared.b16 {%0,%1}, [%2];"
                 : "=r"(r[0]), "=r"(r[1]) : "r"(addr));
}
__device__ __forceinline__ void mma16816(float* d, const uint32_t* a, const uint32_t* b) {
    asm volatile("mma.sync.aligned.m16n8k16.row.col.f32.f16.f16.f32 "
                 "{%0,%1,%2,%3}, {%4,%5,%6,%7}, {%8,%9}, {%0,%1,%2,%3};"
                 : "+f"(d[0]), "+f"(d[1]), "+f"(d[2]), "+f"(d[3])
                 : "r"(a[0]), "r"(a[1]), "r"(a[2]), "r"(a[3]), "r"(b[0]), "r"(b[1]));
}
__device__ __forceinline__ void cp16(uint32_t dst, const void* src) {
    asm volatile("cp.async.cg.shared.global [%0], [%1], 16;" :: "r"(dst), "l"(src));
}
__device__ __forceinline__ void cp_commit() {
    asm volatile("cp.async.commit_group;" ::: "memory");
}
template <int N> __device__ __forceinline__ void cp_wait() {
    asm volatile("cp.async.wait_group %0;" :: "n"(N) : "memory");
}

// ============================================================================
// SMEM layout (dynamic)
// ============================================================================
// actA:  [0, 65536)         128 rows x 256 halves (512B/row, XOR-swizzled)
// actB:  [65536, 131072)
// wbuf0: [131072, 163840)   64 rows x up to 512B/row
// wbuf1: [163840, 196608)
// bias:  [196608, 200704)   4 x 256 fp32
// b4:    [200704, 200720)   3 fp32
// area:  [200720, 201232)   128 fp32
// pred:  [201232, 202768)   128 x 3 fp32
#define SM_ACTA  0
#define SM_ACTB  65536
#define SM_WB0   131072
#define SM_WB1   163840
#define SM_BIAS  196608
#define SM_B4    200704
#define SM_AREA  200720
#define SM_PRED  201232
#define SMEM_BYTES 202768

// chunk = 16B group of 8 halves; swizzle: chunk' = chunk ^ (row & 7)
__device__ __forceinline__ uint32_t swz(int row, int chunk, int rowshift) {
    return ((uint32_t)row << rowshift) + (uint32_t)((chunk ^ (row & 7)) << 4);
}

// ============================================================================
// Fused MLP kernel
// ============================================================================
__global__ void __launch_bounds__(256, 1) liif_mlp(
    const float* __restrict__ coord, const float* __restrict__ cell,
    const float* __restrict__ b0, const float* __restrict__ b1,
    const float* __restrict__ b2, const float* __restrict__ b3,
    const float* __restrict__ b4, float* __restrict__ out)
{
    extern __shared__ char smem[];
    uint32_t sb = smem_u32(smem);
    const int tid = threadIdx.x;
    const int lane = tid & 31;
    const int wid = tid >> 5;
    const int wm = wid & 3;        // 4 warps over 128 rows (32 each)
    const int wn = wid >> 2;       // 2 warps over 64-col quarter (32 each)

    // ---- biases -> smem -----------------------------------------------------
    for (int i = tid; i < 1024; i += 256) {
        int l = i >> 8, n = i & 255;
        const float* p = (l == 0) ? b0 : (l == 1) ? b1 : (l == 2) ? b2 : b3;
        *(float*)(smem + SM_BIAS + i * 4) = p[n];
    }
    if (tid < 3) *(float*)(smem + SM_B4 + tid * 4) = b4[tid];

    // ---- gather prologue: build A0 (128 rows x 80 used cols) ---------------
    {
        int i = tid >> 1;                 // local row 0..127
        int part = tid & 1;
        int r = blockIdx.x * 128 + i;     // global row
        int point = r >> 2, j = r & 3;
        int b = point >> 16, q = point & 65535;
        float c0 = coord[(size_t)(b * Q_ + q) * 2 + 0];
        float c1 = coord[(size_t)(b * Q_ + q) * 2 + 1];
        float rc0 = cell[(size_t)(b * Q_ + q) * 2 + 0] * 128.0f;
        float rc1 = cell[(size_t)(b * Q_ + q) * 2 + 1] * 128.0f;
        const float EPS = 1e-6f, RX = 0.0078125f;
        float sx = ((j & 2) ? RX : -RX) + EPS;
        float sy = ((j & 1) ? RX : -RX) + EPS;
        float lo = -1.0f + EPS, hi = 1.0f - EPS;
        float cs0 = fminf(fmaxf(c0 + sx, lo), hi);
        float cs1 = fminf(fmaxf(c1 + sy, lo), hi);
        int iy = (int)fminf(fmaxf(floorf((cs0 + 1.0f) * 64.0f), 0.0f), 127.0f);
        int ix = (int)fminf(fmaxf(floorf((cs1 + 1.0f) * 64.0f), 0.0f), 127.0f);
        float qc0 = (float)(2 * iy + 1) * 0.0078125f - 1.0f;
        float qc1 = (float)(2 * ix + 1) * 0.0078125f - 1.0f;
        float rel0 = (c0 - qc0) * 128.0f;
        float rel1 = (c1 - qc1) * 128.0f;
        if (part == 0)
            *(float*)(smem + SM_AREA + i * 4) = fabsf(rel0 * rel1) + 1e-9f;

        // copy 64 feats (8 chunks); this thread copies chunks part*4..part*4+3
        const uint4* fp = (const uint4*)(g_featT + ((size_t)((b << 14) + (iy << 7) + ix) << 6));
        #pragma unroll
        for (int u = 0; u < 4; u++) {
            int ch = part * 4 + u;
            *(uint4*)(smem + SM_ACTA + swz(i, ch, 9)) = fp[ch];
        }
        if (part == 1) {
            __half2 h0 = __floats2half2_rn(rel0, rel1);
            __half2 h1 = __floats2half2_rn(rc0, rc1);
            uint4 v;
            v.x = *(uint32_t*)&h0; v.y = *(uint32_t*)&h1; v.z = 0; v.w = 0;
            *(uint4*)(smem + SM_ACTA + swz(i, 8, 9)) = v;
            uint4 z; z.x = z.y = z.z = z.w = 0;
            *(uint4*)(smem + SM_ACTA + swz(i, 9, 9)) = z;
        }
    }

    // ---- weight pass prefetch machinery ------------------------------------
    // pass p in [0,16): layer l=p>>2, quarter q=p&3 (64 n-rows); p==16: W4.
    auto load_pass = [&](int p) {
        const __half* src; int rows, cpr;   // cpr = 16B chunks per row
        if (p < 4)       { src = g_w0i + (p & 3) * 64 * 128; rows = 64; cpr = 16; }
        else if (p < 16) {
            int l = p >> 2, q = p & 3;
            src = (l == 1 ? g_w1i : l == 2 ? g_w2i : g_w3i) + q * 64 * 256;
            rows = 64; cpr = 32;
        } else           { src = g_w4i; rows = 8; cpr = 32; }
        uint32_t dst = sb + ((p & 1) ? SM_WB1 : SM_WB0);
        int total = rows * cpr;
        for (int idx = tid; idx < total; idx += 256) {
            int n = (cpr == 16) ? (idx >> 4) : (idx >> 5);
            int c = idx - n * cpr;
            cp16(dst + (uint32_t)((n * cpr + (c ^ (n & 7))) << 4),
                 (const char*)src + ((size_t)idx << 4));
        }
        cp_commit();
    };

    load_pass(0);

    uint32_t actA = sb + SM_ACTA, actB = sb + SM_ACTB;

    // ---- layers 0..3 (16 quarter-passes, double-buffered weights) ----------
    for (int p = 0; p < 16; ++p) {
        load_pass(p + 1);
        cp_wait<1>();
        __syncthreads();

        const int l = p >> 2, q = p & 3;
        const int ktiles = (l == 0) ? 5 : 16;
        const int wshift = (l == 0) ? 8 : 9;     // log2(W row bytes)
        const uint32_t wBase = sb + ((p & 1) ? SM_WB1 : SM_WB0);

        float acc[2][4][4];
        #pragma unroll
        for (int mt = 0; mt < 2; mt++)
            #pragma unroll
            for (int nt = 0; nt < 4; nt++)
                #pragma unroll
                for (int u = 0; u < 4; u++) acc[mt][nt][u] = 0.0f;

        const int arow = wm * 32 + (lane & 15);
        const int brow0 = wn * 32 + (lane & 7) + ((lane >> 4) << 3);

        for (int kt = 0; kt < ktiles; kt++) {
            uint32_t a[2][4];
            #pragma unroll
            for (int mt = 0; mt < 2; mt++) {
                int row = arow + mt * 16;
                ldsm_x4(a[mt], actA + swz(row, kt * 2 + (lane >> 4), 9));
            }
            uint32_t bfr[4][2];
            #pragma unroll
            for (int bt = 0; bt < 2; bt++) {
                int row = brow0 + bt * 16;
                uint32_t r4[4];
                ldsm_x4(r4, wBase + swz(row, kt * 2 + ((lane >> 3) & 1), wshift));
                bfr[2 * bt][0] = r4[0]; bfr[2 * bt][1] = r4[1];
                bfr[2 * bt + 1][0] = r4[2]; bfr[2 * bt + 1][1] = r4[3];
            }
            #pragma unroll
            for (int mt = 0; mt < 2; mt++)
                #pragma unroll
                for (int nt = 0; nt < 4; nt++)
                    mma16816(acc[mt][nt], a[mt], bfr[nt]);
        }

        // epilogue: bias + ReLU + fp16 -> actB cols [q*64 .. q*64+63]
        {
            const float* bias = (const float*)(smem + SM_BIAS) + l * 256 + q * 64 + wn * 32;
            #pragma unroll
            for (int mt = 0; mt < 2; mt++) {
                int r0 = wm * 32 + mt * 16 + (lane >> 2);
                #pragma unroll
                for (int nt = 0; nt < 4; nt++) {
                    int cloc = wn * 32 + nt * 8 + (lane & 3) * 2;      // col in row
                    int cglob = q * 64 + cloc;
                    float bb0 = bias[nt * 8 + (lane & 3) * 2];
                    float bb1 = bias[nt * 8 + (lane & 3) * 2 + 1];
                    float v0 = fmaxf(acc[mt][nt][0] + bb0, 0.0f);
                    float v1 = fmaxf(acc[mt][nt][1] + bb1, 0.0f);
                    float v2 = fmaxf(acc[mt][nt][2] + bb0, 0.0f);
                    float v3 = fmaxf(acc[mt][nt][3] + bb1, 0.0f);
                    __half2 h01 = __floats2half2_rn(v0, v1);
                    __half2 h23 = __floats2half2_rn(v2, v3);
                    int ch = cglob >> 3, off = (cglob & 7) * 2;
                    *(uint32_t*)(smem + (actB - sb) + swz(r0, ch, 9) + off) = *(uint32_t*)&h01;
                    *(uint32_t*)(smem + (actB - sb) + swz(r0 + 8, ch, 9) + off) = *(uint32_t*)&h23;
                }
            }
        }
        __syncthreads();
        if ((p & 3) == 3) { uint32_t t = actA; actA = actB; actB = t; }
    }

    // ---- final layer: N=8 (real 3), K=256 ----------------------------------
    cp_wait<0>();
    __syncthreads();
    {
        const uint32_t wBase = sb + SM_WB0;   // pass16 loaded into wbuf0 (16&1==0)
        if (wid < 4) {
            float acc[2][4];
            #pragma unroll
            for (int mt = 0; mt < 2; mt++)
                #pragma unroll
                for (int u = 0; u < 4; u++) acc[mt][u] = 0.0f;
            const int arow = wm * 32 + (lane & 15);
            const int brow = lane & 7;
            for (int kt = 0; kt < 16; kt++) {
                uint32_t a[2][4], bf[2];
                #pragma unroll
                for (int mt = 0; mt < 2; mt++)
                    ldsm_x4(a[mt], actA + swz(arow + mt * 16, kt * 2 + (lane >> 4), 9));
                ldsm_x2(bf, wBase + swz(brow, kt * 2 + ((lane >> 3) & 1), 9));
                #pragma unroll
                for (int mt = 0; mt < 2; mt++)
                    mma16816(acc[mt], a[mt], bf);
            }
            // write preds (cols 0..2 real) to smem
            float* pred = (float*)(smem + SM_PRED);
            float* B4 = (float*)(smem + SM_B4);
            #pragma unroll
            for (int mt = 0; mt < 2; mt++) {
                int r0 = wm * 32 + mt * 16 + (lane >> 2);
                int cidx = (lane & 3) * 2;
                if (cidx == 0) {
                    pred[r0 * 3 + 0] = acc[mt][0] + B4[0];
                    pred[r0 * 3 + 1] = acc[mt][1] + B4[1];
                    pred[(r0 + 8) * 3 + 0] = acc[mt][2] + B4[0];
                    pred[(r0 + 8) * 3 + 1] = acc[mt][3] + B4[1];
                } else if (cidx == 2) {
                    pred[r0 * 3 + 2] = acc[mt][0] + B4[2];
                    pred[(r0 + 8) * 3 + 2] = acc[mt][2] + B4[2];
                }
            }
        }
    }
    __syncthreads();

    // ---- combine: 32 points per CTA ----------------------------------------
    if (tid < 32) {
        const float* PR = (const float*)(smem + SM_PRED);
        const float* AR = (const float*)(smem + SM_AREA);
        int base = tid * 4;
        float a0 = AR[base], a1 = AR[base + 1], a2 = AR[base + 2], a3 = AR[base + 3];
        float inv = 1.0f / (a0 + a1 + a2 + a3);
        size_t point = (size_t)blockIdx.x * 32 + tid;
        #pragma unroll
        for (int c = 0; c < 3; c++) {
            float v = PR[(base + 0) * 3 + c] * a3 + PR[(base + 1) * 3 + c] * a2 +
                      PR[(base + 2) * 3 + c] * a1 + PR[(base + 3) * 3 + c] * a0;
            out[point * 3 + c] = v * inv;
        }
    }
}

// ============================================================================
// Launch
// ============================================================================
extern "C" void kernel_launch(void* const* d_in, const int* in_sizes, int n_in,
                              void* d_out, int out_size) {
    const float* feat  = (const float*)d_in[0];
    const float* coord = (const float*)d_in[1];
    const float* cell  = (const float*)d_in[2];
    const float* w0 = (const float*)d_in[3];
    const float* b0 = (const float*)d_in[4];
    const float* w1 = (const float*)d_in[5];
    const float* b1 = (const float*)d_in[6];
    const float* w2 = (const float*)d_in[7];
    const float* b2 = (const float*)d_in[8];
    const float* w3 = (const float*)d_in[9];
    const float* b3 = (const float*)d_in[10];
    const float* w4 = (const float*)d_in[11];
    const float* b4 = (const float*)d_in[12];
    float* out = (float*)d_out;

    static bool attr_set = false;
    if (!attr_set) {
        cudaFuncSetAttribute(liif_mlp, cudaFuncAttributeMaxDynamicSharedMemorySize, SMEM_BYTES);
        attr_set = true;
    }

    prep_feat<<<(B_ * H_ * W_ * C_ + 255) / 256, 256>>>(feat);
    prep_w<<<(32768 + 3 * 65536 + 2048 + 255) / 256, 256>>>(w0, w1, w2, w3, w4);
    liif_mlp<<<8192, 256, SMEM_BYTES>>>(coord, cell, b0, b1, b2, b3, b4, out);
}

// round 4
// speedup vs baseline: 1.1088x; 1.1088x over previous
#include <cuda_runtime.h>
#include <cuda_fp16.h>
#include <cstdint>

// ============================================================================
// Problem constants
// ============================================================================
#define B_   4
#define C_   64
#define H_   128
#define W_   128
#define Q_   65536
#define FEAT_N (B_ * H_ * W_ * C_)              // 1,048,576
#define WTOT   (32768 + 3 * 65536 + 2048)       // 231,424
// rows = 4 branches * B * Q = 1,048,576 ; 128 rows per CTA -> 8192 CTAs

// ============================================================================
// Device scratch (no cudaMalloc allowed)
// ============================================================================
__device__ __align__(16) __half g_featT[(size_t)FEAT_N];   // [B,H,W,C] fp16
__device__ __align__(16) __half g_w0i[256 * 128];  // [n=256][k=128] (real K=68)
__device__ __align__(16) __half g_w1i[256 * 256];  // [n][k]
__device__ __align__(16) __half g_w2i[256 * 256];
__device__ __align__(16) __half g_w3i[256 * 256];
__device__ __align__(16) __half g_w4i[8 * 256];    // [n=8][k=256] (real N=3)

// ============================================================================
// Fused prep kernel (feat transpose->fp16 + weight transpose->fp16)
// ============================================================================
__global__ void prep_all(const float* __restrict__ feat,
                         const float* __restrict__ w0, const float* __restrict__ w1,
                         const float* __restrict__ w2, const float* __restrict__ w3,
                         const float* __restrict__ w4) {
    int o = blockIdx.x * blockDim.x + threadIdx.x;
    if (o < FEAT_N) {
        int c  = o & 63;
        int ix = (o >> 6) & 127;
        int iy = (o >> 13) & 127;
        int b  = o >> 20;
        g_featT[o] = __float2half(feat[(((size_t)b * C_ + c) * H_ + iy) * W_ + ix]);
        return;
    }
    int i = o - FEAT_N;
    if (i < 32768) {                        // W0: [256][128], real K=68
        int n = i >> 7, k = i & 127;
        g_w0i[i] = __float2half(k < 68 ? w0[k * 256 + n] : 0.0f);
    } else if (i < 32768 + 3 * 65536) {     // W1..W3: [256][256]
        int j = i - 32768;
        int l = j >> 16; j &= 65535;
        int n = j >> 8, k = j & 255;
        const float* w = (l == 0) ? w1 : ((l == 1) ? w2 : w3);
        __half* d = (l == 0) ? g_w1i : ((l == 1) ? g_w2i : g_w3i);
        d[j] = __float2half(w[k * 256 + n]);
    } else if (i < WTOT) {                  // W4: [8][256], real N=3
        int j = i - 32768 - 3 * 65536;
        int n = j >> 8, k = j & 255;
        g_w4i[j] = __float2half(n < 3 ? w4[k * 3 + n] : 0.0f);
    }
}

// ============================================================================
// PTX wrappers (baseline PTX: sm_80/sm_90 class, valid at compute_103)
// ============================================================================
__device__ __forceinline__ uint32_t smem_u32(const void* p) {
    uint32_t a;
    asm("{ .reg .u64 t; cvta.to.shared.u64 t, %1; cvt.u32.u64 %0, t; }" : "=r"(a) : "l"(p));
    return a;
}
__device__ __forceinline__ void ldsm_x4(uint32_t* r, uint32_t addr) {
    asm volatile("ldmatrix.sync.aligned.m8n8.x4.shared.b16 {%0,%1,%2,%3}, [%4];"
                 : "=r"(r[0]), "=r"(r[1]), "=r"(r[2]), "=r"(r[3]) : "r"(addr));
}
__device__ __forceinline__ void ldsm_x2(uint32_t* r, uint32_t addr) {
    asm volatile("ldmatrix.sync.aligned.m8n8.x2.shared.b16 {%0,%1}, [%2];"
                 : "=r"(r[0]), "=r"(r[1]) : "r"(addr));
}
__device__ __forceinline__ void stsm_x4(uint32_t addr, uint32_t r0, uint32_t r1,
                                        uint32_t r2, uint32_t r3) {
    asm volatile("stmatrix.sync.aligned.m8n8.x4.shared.b16 [%0], {%1,%2,%3,%4};"
                 :: "r"(addr), "r"(r0), "r"(r1), "r"(r2), "r"(r3) : "memory");
}
__device__ __forceinline__ void mma16816(float* d, const uint32_t* a, const uint32_t* b) {
    asm volatile("mma.sync.aligned.m16n8k16.row.col.f32.f16.f16.f32 "
                 "{%0,%1,%2,%3}, {%4,%5,%6,%7}, {%8,%9}, {%0,%1,%2,%3};"
                 : "+f"(d[0]), "+f"(d[1]), "+f"(d[2]), "+f"(d[3])
                 : "r"(a[0]), "r"(a[1]), "r"(a[2]), "r"(a[3]), "r"(b[0]), "r"(b[1]));
}
__device__ __forceinline__ void cp16(uint32_t dst, const void* src) {
    asm volatile("cp.async.cg.shared.global [%0], [%1], 16;" :: "r"(dst), "l"(src));
}
__device__ __forceinline__ void cp_commit() {
    asm volatile("cp.async.commit_group;" ::: "memory");
}
template <int N> __device__ __forceinline__ void cp_wait() {
    asm volatile("cp.async.wait_group %0;" :: "n"(N) : "memory");
}

// ============================================================================
// SMEM layout (dynamic)
// ============================================================================
#define SM_ACTA  0
#define SM_ACTB  65536
#define SM_WB0   131072
#define SM_WB1   163840
#define SM_BIAS  196608
#define SM_B4    200704
#define SM_AREA  200720
#define SM_PRED  201232
#define SMEM_BYTES 202768

// chunk = 16B group of 8 halves; swizzle: chunk' = chunk ^ (row & 7)
__device__ __forceinline__ uint32_t swz(int row, int chunk, int rowshift) {
    return ((uint32_t)row << rowshift) + (uint32_t)((chunk ^ (row & 7)) << 4);
}

// ============================================================================
// Fused MLP kernel: 128 rows/CTA, 8 warps (wm: 4x32 rows, wn: 2x32 cols)
// ============================================================================
__global__ void __launch_bounds__(256, 1) liif_mlp(
    const float* __restrict__ coord, const float* __restrict__ cell,
    const float* __restrict__ b0, const float* __restrict__ b1,
    const float* __restrict__ b2, const float* __restrict__ b3,
    const float* __restrict__ b4, float* __restrict__ out)
{
    extern __shared__ char smem[];
    uint32_t sb = smem_u32(smem);
    const int tid = threadIdx.x;
    const int lane = tid & 31;
    const int wid = tid >> 5;
    const int wm = wid & 3;        // 4 warps over 128 rows (32 each)
    const int wn = wid >> 2;       // 2 warps over 64-col quarter (32 each)

    // ---- biases -> smem -----------------------------------------------------
    for (int i = tid; i < 1024; i += 256) {
        int l = i >> 8, n = i & 255;
        const float* p = (l == 0) ? b0 : (l == 1) ? b1 : (l == 2) ? b2 : b3;
        *(float*)(smem + SM_BIAS + i * 4) = p[n];
    }
    if (tid < 3) *(float*)(smem + SM_B4 + tid * 4) = b4[tid];

    // ---- gather prologue: build A0 (128 rows x 80 used cols) ---------------
    {
        int i = tid >> 1;                 // local row 0..127
        int part = tid & 1;
        int r = blockIdx.x * 128 + i;     // global row
        int point = r >> 2, j = r & 3;
        int b = point >> 16, q = point & 65535;
        float c0 = coord[(size_t)(b * Q_ + q) * 2 + 0];
        float c1 = coord[(size_t)(b * Q_ + q) * 2 + 1];
        float rc0 = cell[(size_t)(b * Q_ + q) * 2 + 0] * 128.0f;
        float rc1 = cell[(size_t)(b * Q_ + q) * 2 + 1] * 128.0f;
        const float EPS = 1e-6f, RX = 0.0078125f;
        float sx = ((j & 2) ? RX : -RX) + EPS;
        float sy = ((j & 1) ? RX : -RX) + EPS;
        float lo = -1.0f + EPS, hi = 1.0f - EPS;
        float cs0 = fminf(fmaxf(c0 + sx, lo), hi);
        float cs1 = fminf(fmaxf(c1 + sy, lo), hi);
        int iy = (int)fminf(fmaxf(floorf((cs0 + 1.0f) * 64.0f), 0.0f), 127.0f);
        int ix = (int)fminf(fmaxf(floorf((cs1 + 1.0f) * 64.0f), 0.0f), 127.0f);
        float qc0 = (float)(2 * iy + 1) * 0.0078125f - 1.0f;
        float qc1 = (float)(2 * ix + 1) * 0.0078125f - 1.0f;
        float rel0 = (c0 - qc0) * 128.0f;
        float rel1 = (c1 - qc1) * 128.0f;
        if (part == 0)
            *(float*)(smem + SM_AREA + i * 4) = fabsf(rel0 * rel1) + 1e-9f;

        const uint4* fp = (const uint4*)(g_featT + ((size_t)((b << 14) + (iy << 7) + ix) << 6));
        #pragma unroll
        for (int u = 0; u < 4; u++) {
            int ch = part * 4 + u;
            *(uint4*)(smem + SM_ACTA + swz(i, ch, 9)) = fp[ch];
        }
        if (part == 1) {
            __half2 h0 = __floats2half2_rn(rel0, rel1);
            __half2 h1 = __floats2half2_rn(rc0, rc1);
            uint4 v;
            v.x = *(uint32_t*)&h0; v.y = *(uint32_t*)&h1; v.z = 0; v.w = 0;
            *(uint4*)(smem + SM_ACTA + swz(i, 8, 9)) = v;
            uint4 z; z.x = z.y = z.z = z.w = 0;
            *(uint4*)(smem + SM_ACTA + swz(i, 9, 9)) = z;
        }
    }

    // ---- weight pass prefetch machinery ------------------------------------
    auto load_pass = [&](int p) {
        const __half* src; int rows, cpr;   // cpr = 16B chunks per row
        if (p < 4)       { src = g_w0i + (p & 3) * 64 * 128; rows = 64; cpr = 16; }
        else if (p < 16) {
            int l = p >> 2, q = p & 3;
            src = (l == 1 ? g_w1i : l == 2 ? g_w2i : g_w3i) + q * 64 * 256;
            rows = 64; cpr = 32;
        } else           { src = g_w4i; rows = 8; cpr = 32; }
        uint32_t dst = sb + ((p & 1) ? SM_WB1 : SM_WB0);
        int total = rows * cpr;
        for (int idx = tid; idx < total; idx += 256) {
            int n = (cpr == 16) ? (idx >> 4) : (idx >> 5);
            int c = idx - n * cpr;
            cp16(dst + (uint32_t)((n * cpr + (c ^ (n & 7))) << 4),
                 (const char*)src + ((size_t)idx << 4));
        }
        cp_commit();
    };

    load_pass(0);

    uint32_t actA = sb + SM_ACTA, actB = sb + SM_ACTB;

    const int arow = wm * 32 + (lane & 15);
    const int brow0 = wn * 32 + (lane & 7) + ((lane >> 4) << 3);

    // ---- layers 0..3 (16 quarter-passes, double-buffered weights) ----------
    for (int p = 0; p < 16; ++p) {
        load_pass(p + 1);
        cp_wait<1>();
        __syncthreads();

        const int l = p >> 2, q = p & 3;
        const int ktiles = (l == 0) ? 5 : 16;
        const int wshift = (l == 0) ? 8 : 9;     // log2(W row bytes)
        const uint32_t wBase = sb + ((p & 1) ? SM_WB1 : SM_WB0);

        float acc[2][4][4];
        #pragma unroll
        for (int mt = 0; mt < 2; mt++)
            #pragma unroll
            for (int nt = 0; nt < 4; nt++)
                #pragma unroll
                for (int u = 0; u < 4; u++) acc[mt][nt][u] = 0.0f;

        // fragment loader (A: 2 x ldsm_x4, B: 2 x ldsm_x4)
        auto load_frags = [&](int kt, uint32_t a[][4], uint32_t bfr[][2]) {
            #pragma unroll
            for (int mt = 0; mt < 2; mt++)
                ldsm_x4(a[mt], actA + swz(arow + mt * 16, kt * 2 + (lane >> 4), 9));
            #pragma unroll
            for (int bt = 0; bt < 2; bt++) {
                uint32_t r4[4];
                ldsm_x4(r4, wBase + swz(brow0 + bt * 16, kt * 2 + ((lane >> 3) & 1), wshift));
                bfr[2 * bt][0] = r4[0]; bfr[2 * bt][1] = r4[1];
                bfr[2 * bt + 1][0] = r4[2]; bfr[2 * bt + 1][1] = r4[3];
            }
        };
        auto mma_all = [&](uint32_t a[][4], uint32_t bfr[][2]) {
            #pragma unroll
            for (int mt = 0; mt < 2; mt++)
                #pragma unroll
                for (int nt = 0; nt < 4; nt++)
                    mma16816(acc[mt][nt], a[mt], bfr[nt]);
        };

        // software-pipelined k loop (2-deep register double buffer)
        uint32_t a0[2][4], b0f[4][2], a1[2][4], b1f[4][2];
        load_frags(0, a0, b0f);
        for (int kt = 0; kt < ktiles; kt += 2) {
            if (kt + 1 < ktiles) load_frags(kt + 1, a1, b1f);
            mma_all(a0, b0f);
            if (kt + 1 < ktiles) {
                if (kt + 2 < ktiles) load_frags(kt + 2, a0, b0f);
                mma_all(a1, b1f);
            }
        }

        // epilogue: bias + ReLU + fp16, then stmatrix into actB quarter q
        {
            const float* bias = (const float*)(smem + SM_BIAS) + l * 256 + q * 64 + wn * 32;
            const int g = lane >> 3, lr = lane & 7;
            #pragma unroll
            for (int mt = 0; mt < 2; mt++) {
                uint32_t h01[4], h23[4];
                #pragma unroll
                for (int nt = 0; nt < 4; nt++) {
                    float bb0 = bias[nt * 8 + (lane & 3) * 2];
                    float bb1 = bias[nt * 8 + (lane & 3) * 2 + 1];
                    float v0 = fmaxf(acc[mt][nt][0] + bb0, 0.0f);
                    float v1 = fmaxf(acc[mt][nt][1] + bb1, 0.0f);
                    float v2 = fmaxf(acc[mt][nt][2] + bb0, 0.0f);
                    float v3 = fmaxf(acc[mt][nt][3] + bb1, 0.0f);
                    __half2 p01 = __floats2half2_rn(v0, v1);
                    __half2 p23 = __floats2half2_rn(v2, v3);
                    h01[nt] = *(uint32_t*)&p01;
                    h23[nt] = *(uint32_t*)&p23;
                }
                #pragma unroll
                for (int npair = 0; npair < 2; npair++) {
                    int row = wm * 32 + mt * 16 + ((g & 1) << 3) + lr;
                    int chunk = q * 8 + wn * 4 + npair * 2 + (g >> 1);
                    uint32_t ad = actB + swz(row, chunk, 9);
                    stsm_x4(ad, h01[2 * npair], h23[2 * npair],
                                h01[2 * npair + 1], h23[2 * npair + 1]);
                }
            }
        }
        __syncthreads();
        if ((p & 3) == 3) { uint32_t t = actA; actA = actB; actB = t; }
    }

    // ---- final layer: N=8 (real 3), K=256 ----------------------------------
    cp_wait<0>();
    __syncthreads();
    {
        const uint32_t wBase = sb + SM_WB0;   // pass16 loaded into wbuf0
        if (wid < 4) {
            float acc[2][4];
            #pragma unroll
            for (int mt = 0; mt < 2; mt++)
                #pragma unroll
                for (int u = 0; u < 4; u++) acc[mt][u] = 0.0f;
            const int arw = wm * 32 + (lane & 15);
            const int brw = lane & 7;
            uint32_t a0[2][4], bf0[2], a1[2][4], bf1[2];
            auto ldf = [&](int kt, uint32_t a[][4], uint32_t* bf) {
                #pragma unroll
                for (int mt = 0; mt < 2; mt++)
                    ldsm_x4(a[mt], actA + swz(arw + mt * 16, kt * 2 + (lane >> 4), 9));
                ldsm_x2(bf, wBase + swz(brw, kt * 2 + ((lane >> 3) & 1), 9));
            };
            ldf(0, a0, bf0);
            for (int kt = 0; kt < 16; kt += 2) {
                if (kt + 1 < 16) ldf(kt + 1, a1, bf1);
                #pragma unroll
                for (int mt = 0; mt < 2; mt++) mma16816(acc[mt], a0[mt], bf0);
                if (kt + 2 < 16) ldf(kt + 2, a0, bf0);
                #pragma unroll
                for (int mt = 0; mt < 2; mt++) mma16816(acc[mt], a1[mt], bf1);
            }
            float* pred = (float*)(smem + SM_PRED);
            float* B4 = (float*)(smem + SM_B4);
            #pragma unroll
            for (int mt = 0; mt < 2; mt++) {
                int r0 = wm * 32 + mt * 16 + (lane >> 2);
                int cidx = (lane & 3) * 2;
                if (cidx == 0) {
                    pred[r0 * 3 + 0] = acc[mt][0] + B4[0];
                    pred[r0 * 3 + 1] = acc[mt][1] + B4[1];
                    pred[(r0 + 8) * 3 + 0] = acc[mt][2] + B4[0];
                    pred[(r0 + 8) * 3 + 1] = acc[mt][3] + B4[1];
                } else if (cidx == 2) {
                    pred[r0 * 3 + 2] = acc[mt][0] + B4[2];
                    pred[(r0 + 8) * 3 + 2] = acc[mt][2] + B4[2];
                }
            }
        }
    }
    __syncthreads();

    // ---- combine: 32 points per CTA ----------------------------------------
    if (tid < 32) {
        const float* PR = (const float*)(smem + SM_PRED);
        const float* AR = (const float*)(smem + SM_AREA);
        int base = tid * 4;
        float a0 = AR[base], a1 = AR[base + 1], a2 = AR[base + 2], a3 = AR[base + 3];
        float inv = 1.0f / (a0 + a1 + a2 + a3);
        size_t point = (size_t)blockIdx.x * 32 + tid;
        #pragma unroll
        for (int c = 0; c < 3; c++) {
            float v = PR[(base + 0) * 3 + c] * a3 + PR[(base + 1) * 3 + c] * a2 +
                      PR[(base + 2) * 3 + c] * a1 + PR[(base + 3) * 3 + c] * a0;
            out[point * 3 + c] = v * inv;
        }
    }
}

// ============================================================================
// Launch
// ============================================================================
extern "C" void kernel_launch(void* const* d_in, const int* in_sizes, int n_in,
                              void* d_out, int out_size) {
    const float* feat  = (const float*)d_in[0];
    const float* coord = (const float*)d_in[1];
    const float* cell  = (const float*)d_in[2];
    const float* w0 = (const float*)d_in[3];
    const float* b0 = (const float*)d_in[4];
    const float* w1 = (const float*)d_in[5];
    const float* b1 = (const float*)d_in[6];
    const float* w2 = (const float*)d_in[7];
    const float* b2 = (const float*)d_in[8];
    const float* w3 = (const float*)d_in[9];
    const float* b3 = (const float*)d_in[10];
    const float* w4 = (const float*)d_in[11];
    const float* b4 = (const float*)d_in[12];
    float* out = (float*)d_out;

    static bool attr_set = false;
    if (!attr_set) {
        cudaFuncSetAttribute(liif_mlp, cudaFuncAttributeMaxDynamicSharedMemorySize, SMEM_BYTES);
        attr_set = true;
    }

    prep_all<<<(FEAT_N + WTOT + 255) / 256, 256>>>(feat, w0, w1, w2, w3, w4);
    liif_mlp<<<8192, 256, SMEM_BYTES>>>(coord, cell, b0, b1, b2, b3, b4, out);
}

// round 5
// speedup vs baseline: 1.3267x; 1.1965x over previous
#include <cuda_runtime.h>
#include <cuda_fp16.h>
#include <cstdint>

// ============================================================================
// Problem constants
// ============================================================================
#define B_   4
#define C_   64
#define H_   128
#define W_   128
#define Q_   65536
#define FEAT_N (B_ * H_ * W_ * C_)              // 1,048,576
#define WTOT   (32768 + 3 * 65536 + 2048)       // 231,424
// rows = 4 branches * B * Q = 1,048,576 ; 128 rows per CTA -> 8192 CTAs

// ============================================================================
// Device scratch (no cudaMalloc allowed)
// ============================================================================
__device__ __align__(16) __half g_featT[(size_t)FEAT_N];   // [B,H,W,C] fp16
__device__ __align__(16) __half g_w0i[256 * 128];  // [n=256][k=128] (real K=68)
__device__ __align__(16) __half g_w1i[256 * 256];  // [n][k]
__device__ __align__(16) __half g_w2i[256 * 256];
__device__ __align__(16) __half g_w3i[256 * 256];
__device__ __align__(16) __half g_w4i[8 * 256];    // [n=8][k=256] (real N=3)

// ============================================================================
// Fused prep kernel
// ============================================================================
__global__ void prep_all(const float* __restrict__ feat,
                         const float* __restrict__ w0, const float* __restrict__ w1,
                         const float* __restrict__ w2, const float* __restrict__ w3,
                         const float* __restrict__ w4) {
    int o = blockIdx.x * blockDim.x + threadIdx.x;
    if (o < FEAT_N) {
        int c  = o & 63;
        int ix = (o >> 6) & 127;
        int iy = (o >> 13) & 127;
        int b  = o >> 20;
        g_featT[o] = __float2half(feat[(((size_t)b * C_ + c) * H_ + iy) * W_ + ix]);
        return;
    }
    int i = o - FEAT_N;
    if (i < 32768) {                        // W0: [256][128], real K=68
        int n = i >> 7, k = i & 127;
        g_w0i[i] = __float2half(k < 68 ? w0[k * 256 + n] : 0.0f);
    } else if (i < 32768 + 3 * 65536) {     // W1..W3: [256][256]
        int j = i - 32768;
        int l = j >> 16; j &= 65535;
        int n = j >> 8, k = j & 255;
        const float* w = (l == 0) ? w1 : ((l == 1) ? w2 : w3);
        __half* d = (l == 0) ? g_w1i : ((l == 1) ? g_w2i : g_w3i);
        d[j] = __float2half(w[k * 256 + n]);
    } else if (i < WTOT) {                  // W4: [8][256], real N=3
        int j = i - 32768 - 3 * 65536;
        int n = j >> 8, k = j & 255;
        g_w4i[j] = __float2half(n < 3 ? w4[k * 3 + n] : 0.0f);
    }
}

// ============================================================================
// PTX wrappers (baseline PTX, valid at compute_103)
// ============================================================================
__device__ __forceinline__ uint32_t smem_u32(const void* p) {
    uint32_t a;
    asm("{ .reg .u64 t; cvta.to.shared.u64 t, %1; cvt.u32.u64 %0, t; }" : "=r"(a) : "l"(p));
    return a;
}
__device__ __forceinline__ void ldsm_x4(uint32_t* r, uint32_t addr) {
    asm volatile("ldmatrix.sync.aligned.m8n8.x4.shared.b16 {%0,%1,%2,%3}, [%4];"
                 : "=r"(r[0]), "=r"(r[1]), "=r"(r[2]), "=r"(r[3]) : "r"(addr));
}
__device__ __forceinline__ void ldsm_x2(uint32_t* r, uint32_t addr) {
    asm volatile("ldmatrix.sync.aligned.m8n8.x2.shared.b16 {%0,%1}, [%2];"
                 : "=r"(r[0]), "=r"(r[1]) : "r"(addr));
}
__device__ __forceinline__ void stsm_x4(uint32_t addr, uint32_t r0, uint32_t r1,
                                        uint32_t r2, uint32_t r3) {
    asm volatile("stmatrix.sync.aligned.m8n8.x4.shared.b16 [%0], {%1,%2,%3,%4};"
                 :: "r"(addr), "r"(r0), "r"(r1), "r"(r2), "r"(r3) : "memory");
}
__device__ __forceinline__ void mma16816(float* d, const uint32_t* a, const uint32_t* b) {
    asm volatile("mma.sync.aligned.m16n8k16.row.col.f32.f16.f16.f32 "
                 "{%0,%1,%2,%3}, {%4,%5,%6,%7}, {%8,%9}, {%0,%1,%2,%3};"
                 : "+f"(d[0]), "+f"(d[1]), "+f"(d[2]), "+f"(d[3])
                 : "r"(a[0]), "r"(a[1]), "r"(a[2]), "r"(a[3]), "r"(b[0]), "r"(b[1]));
}
__device__ __forceinline__ void cp16(uint32_t dst, const void* src) {
    asm volatile("cp.async.cg.shared.global [%0], [%1], 16;" :: "r"(dst), "l"(src));
}
__device__ __forceinline__ void cp_commit() {
    asm volatile("cp.async.commit_group;" ::: "memory");
}
template <int N> __device__ __forceinline__ void cp_wait() {
    asm volatile("cp.async.wait_group %0;" :: "n"(N) : "memory");
}

// ============================================================================
// SMEM layout (dynamic)
// ============================================================================
// act : [0, 65536)          128 rows x 256 halves (512B/row, swizzled), single buffer
// wb0 : [65536, 131072)     half-layer weights (128 n-rows x up to 512B)
// wb1 : [131072, 196608)
// bias/b4/area/pred tail
#define SM_ACT   0
#define SM_WB0   65536
#define SM_WB1   131072
#define SM_BIAS  196608
#define SM_B4    200704
#define SM_AREA  200720
#define SM_PRED  201232
#define SMEM_BYTES 202768

// chunk = 16B group of 8 halves; swizzle: chunk' = chunk ^ (row & 7)
__device__ __forceinline__ uint32_t swz(int row, int chunk, int rowshift) {
    return ((uint32_t)row << rowshift) + (uint32_t)((chunk ^ (row & 7)) << 4);
}

// ============================================================================
// Half-layer compute: warp tile 64 rows x 32 cols, K = KT*16, output held in regs
// ============================================================================
template <int KT, int WSHIFT>
__device__ __forceinline__ void compute_half(
    uint32_t act, uint32_t wBase, const float* bias,
    int arowb, int brow0, int lane,
    uint32_t (&o01)[4][4], uint32_t (&o23)[4][4])
{
    float acc[4][4][4];
    #pragma unroll
    for (int mt = 0; mt < 4; mt++)
        #pragma unroll
        for (int nt = 0; nt < 4; nt++)
            #pragma unroll
            for (int u = 0; u < 4; u++) acc[mt][nt][u] = 0.0f;

    uint32_t a[2][4][4];
    uint32_t bf[2][4][2];

    auto ldf = [&](int kt, int s) {
        #pragma unroll
        for (int mt = 0; mt < 4; mt++)
            ldsm_x4(a[s][mt], act + swz(arowb + mt * 16, kt * 2 + (lane >> 4), 9));
        #pragma unroll
        for (int bt = 0; bt < 2; bt++) {
            uint32_t r4[4];
            ldsm_x4(r4, wBase + swz(brow0 + bt * 16, kt * 2 + ((lane >> 3) & 1), WSHIFT));
            bf[s][2 * bt][0] = r4[0]; bf[s][2 * bt][1] = r4[1];
            bf[s][2 * bt + 1][0] = r4[2]; bf[s][2 * bt + 1][1] = r4[3];
        }
    };

    ldf(0, 0);
    #pragma unroll
    for (int kt = 0; kt < KT; kt++) {
        const int cur = kt & 1;
        if (kt + 1 < KT) ldf(kt + 1, cur ^ 1);
        #pragma unroll
        for (int mt = 0; mt < 4; mt++)
            #pragma unroll
            for (int nt = 0; nt < 4; nt++)
                mma16816(acc[mt][nt], a[cur][mt], bf[cur][nt]);
    }

    // bias + ReLU + fp16 pack (held in registers)
    #pragma unroll
    for (int mt = 0; mt < 4; mt++)
        #pragma unroll
        for (int nt = 0; nt < 4; nt++) {
            float bb0 = bias[nt * 8 + (lane & 3) * 2];
            float bb1 = bias[nt * 8 + (lane & 3) * 2 + 1];
            float v0 = fmaxf(acc[mt][nt][0] + bb0, 0.0f);
            float v1 = fmaxf(acc[mt][nt][1] + bb1, 0.0f);
            float v2 = fmaxf(acc[mt][nt][2] + bb0, 0.0f);
            float v3 = fmaxf(acc[mt][nt][3] + bb1, 0.0f);
            __half2 p01 = __floats2half2_rn(v0, v1);
            __half2 p23 = __floats2half2_rn(v2, v3);
            o01[mt][nt] = *(uint32_t*)&p01;
            o23[mt][nt] = *(uint32_t*)&p23;
        }
}

// ============================================================================
// Fused MLP kernel: 128 rows/CTA, 8 warps (wm 2x64 rows, wn 4x32 cols)
// 9 half-layer passes, weights double-buffered (2x64KB), act single (64KB).
// ============================================================================
__global__ void __launch_bounds__(256, 1) liif_mlp(
    const float* __restrict__ coord, const float* __restrict__ cell,
    const float* __restrict__ b0, const float* __restrict__ b1,
    const float* __restrict__ b2, const float* __restrict__ b3,
    const float* __restrict__ b4, float* __restrict__ out)
{
    extern __shared__ char smem[];
    uint32_t sb = smem_u32(smem);
    const int tid = threadIdx.x;
    const int lane = tid & 31;
    const int wid = tid >> 5;
    const int wm = wid >> 2;       // 2 groups x 64 rows
    const int wn = wid & 3;        // 4 groups x 32 cols within a 128-col half

    // ---- weight pass prefetch: pass i (0..8), buffer = i&1 ------------------
    auto load_pass = [&](int p) {
        const __half* src; int rows, cpr;   // cpr = 16B chunks per row
        if (p < 2)      { src = g_w0i + p * 128 * 128; rows = 128; cpr = 16; }
        else if (p < 8) {
            int l = p >> 1, h = p & 1;
            src = (l == 1 ? g_w1i : l == 2 ? g_w2i : g_w3i) + h * 128 * 256;
            rows = 128; cpr = 32;
        } else          { src = g_w4i; rows = 8; cpr = 32; }
        uint32_t dst = sb + ((p & 1) ? SM_WB1 : SM_WB0);
        int total = rows * cpr;
        for (int idx = tid; idx < total; idx += 256) {
            int n = (cpr == 16) ? (idx >> 4) : (idx >> 5);
            int c = idx - n * cpr;
            cp16(dst + (uint32_t)((n * cpr + (c ^ (n & 7))) << 4),
                 (const char*)src + ((size_t)idx << 4));
        }
        cp_commit();
    };

    load_pass(0);
    load_pass(1);

    // ---- biases -> smem -----------------------------------------------------
    for (int i = tid; i < 1024; i += 256) {
        int l = i >> 8, n = i & 255;
        const float* p = (l == 0) ? b0 : (l == 1) ? b1 : (l == 2) ? b2 : b3;
        *(float*)(smem + SM_BIAS + i * 4) = p[n];
    }
    if (tid < 3) *(float*)(smem + SM_B4 + tid * 4) = b4[tid];

    // ---- gather prologue: build A0 (128 rows x 80 used cols) ---------------
    {
        int i = tid >> 1;                 // local row 0..127
        int part = tid & 1;
        int r = blockIdx.x * 128 + i;     // global row
        int point = r >> 2, j = r & 3;
        int b = point >> 16, q = point & 65535;
        float c0 = coord[(size_t)(b * Q_ + q) * 2 + 0];
        float c1 = coord[(size_t)(b * Q_ + q) * 2 + 1];
        float rc0 = cell[(size_t)(b * Q_ + q) * 2 + 0] * 128.0f;
        float rc1 = cell[(size_t)(b * Q_ + q) * 2 + 1] * 128.0f;
        const float EPS = 1e-6f, RX = 0.0078125f;
        float sx = ((j & 2) ? RX : -RX) + EPS;
        float sy = ((j & 1) ? RX : -RX) + EPS;
        float lo = -1.0f + EPS, hi = 1.0f - EPS;
        float cs0 = fminf(fmaxf(c0 + sx, lo), hi);
        float cs1 = fminf(fmaxf(c1 + sy, lo), hi);
        int iy = (int)fminf(fmaxf(floorf((cs0 + 1.0f) * 64.0f), 0.0f), 127.0f);
        int ix = (int)fminf(fmaxf(floorf((cs1 + 1.0f) * 64.0f), 0.0f), 127.0f);
        float qc0 = (float)(2 * iy + 1) * 0.0078125f - 1.0f;
        float qc1 = (float)(2 * ix + 1) * 0.0078125f - 1.0f;
        float rel0 = (c0 - qc0) * 128.0f;
        float rel1 = (c1 - qc1) * 128.0f;
        if (part == 0)
            *(float*)(smem + SM_AREA + i * 4) = fabsf(rel0 * rel1) + 1e-9f;

        const uint4* fp = (const uint4*)(g_featT + ((size_t)((b << 14) + (iy << 7) + ix) << 6));
        #pragma unroll
        for (int u = 0; u < 4; u++) {
            int ch = part * 4 + u;
            *(uint4*)(smem + SM_ACT + swz(i, ch, 9)) = fp[ch];
        }
        if (part == 1) {
            __half2 h0 = __floats2half2_rn(rel0, rel1);
            __half2 h1 = __floats2half2_rn(rc0, rc1);
            uint4 v;
            v.x = *(uint32_t*)&h0; v.y = *(uint32_t*)&h1; v.z = 0; v.w = 0;
            *(uint4*)(smem + SM_ACT + swz(i, 8, 9)) = v;
            uint4 z; z.x = z.y = z.z = z.w = 0;
            *(uint4*)(smem + SM_ACT + swz(i, 9, 9)) = z;
        }
    }

    cp_wait<1>();        // pass 0 weights arrived (pass 1 may be in flight)
    __syncthreads();     // + gather visible to all

    const uint32_t act = sb + SM_ACT;
    const int arowb = wm * 64 + (lane & 15);
    const int brow0 = wn * 32 + (lane & 7) + ((lane >> 4) << 3);
    const int g = lane >> 3, lr = lane & 7;

    uint32_t h01[2][4][4], h23[2][4][4];

    // ---- layers 0..3: two half-passes each, outputs held in registers ------
    #pragma unroll 1
    for (int l = 0; l < 4; l++) {
        const float* biasl = (const float*)(smem + SM_BIAS) + l * 256 + wn * 32;

        // half 0 (weights in WB0)
        if (l == 0)
            compute_half<5, 8>(act, sb + SM_WB0, biasl, arowb, brow0, lane, h01[0], h23[0]);
        else
            compute_half<16, 9>(act, sb + SM_WB0, biasl, arowb, brow0, lane, h01[0], h23[0]);
        __syncthreads();                       // all warps done reading WB0
        if (2 * l + 2 <= 8) load_pass(2 * l + 2);   // next-next pass -> WB0
        cp_wait<1>();                          // half-1 weights (WB1) complete
        __syncthreads();                       // visible to all threads

        // half 1 (weights in WB1)
        if (l == 0)
            compute_half<5, 8>(act, sb + SM_WB1, biasl + 128, arowb, brow0, lane, h01[1], h23[1]);
        else
            compute_half<16, 9>(act, sb + SM_WB1, biasl + 128, arowb, brow0, lane, h01[1], h23[1]);
        __syncthreads();                       // all reads of act + WB1 done
        if (2 * l + 3 <= 8) load_pass(2 * l + 3);   // -> WB1

        // write both halves into act (overwrite) via stmatrix
        #pragma unroll
        for (int h = 0; h < 2; h++)
            #pragma unroll
            for (int mt = 0; mt < 4; mt++)
                #pragma unroll
                for (int np = 0; np < 2; np++) {
                    int row = wm * 64 + mt * 16 + ((g & 1) << 3) + lr;
                    int chunk = h * 16 + wn * 4 + np * 2 + (g >> 1);
                    stsm_x4(act + swz(row, chunk, 9),
                            h01[h][mt][2 * np], h23[h][mt][2 * np],
                            h01[h][mt][2 * np + 1], h23[h][mt][2 * np + 1]);
                }
        if (l < 3) cp_wait<1>(); else cp_wait<0>();  // next h0 weights ready
        __syncthreads();                              // stmatrix + weights visible
    }

    // ---- final layer: N=8 (real 3), K=256, weights in WB0 ------------------
    {
        const uint32_t wBase = sb + SM_WB0;
        if (wid < 4) {
            float acc[2][4];
            #pragma unroll
            for (int mt = 0; mt < 2; mt++)
                #pragma unroll
                for (int u = 0; u < 4; u++) acc[mt][u] = 0.0f;
            const int arw = wid * 32 + (lane & 15);
            const int brw = lane & 7;
            uint32_t a0[2][4], bf0[2], a1[2][4], bf1[2];
            auto ldf = [&](int kt, uint32_t a[][4], uint32_t* bf) {
                #pragma unroll
                for (int mt = 0; mt < 2; mt++)
                    ldsm_x4(a[mt], act + swz(arw + mt * 16, kt * 2 + (lane >> 4), 9));
                ldsm_x2(bf, wBase + swz(brw, kt * 2 + ((lane >> 3) & 1), 9));
            };
            ldf(0, a0, bf0);
            #pragma unroll
            for (int kt = 0; kt < 16; kt += 2) {
                if (kt + 1 < 16) ldf(kt + 1, a1, bf1);
                #pragma unroll
                for (int mt = 0; mt < 2; mt++) mma16816(acc[mt], a0[mt], bf0);
                if (kt + 2 < 16) ldf(kt + 2, a0, bf0);
                #pragma unroll
                for (int mt = 0; mt < 2; mt++) mma16816(acc[mt], a1[mt], bf1);
            }
            float* pred = (float*)(smem + SM_PRED);
            float* B4 = (float*)(smem + SM_B4);
            #pragma unroll
            for (int mt = 0; mt < 2; mt++) {
                int r0 = wid * 32 + mt * 16 + (lane >> 2);
                int cidx = (lane & 3) * 2;
                if (cidx == 0) {
                    pred[r0 * 3 + 0] = acc[mt][0] + B4[0];
                    pred[r0 * 3 + 1] = acc[mt][1] + B4[1];
                    pred[(r0 + 8) * 3 + 0] = acc[mt][2] + B4[0];
                    pred[(r0 + 8) * 3 + 1] = acc[mt][3] + B4[1];
                } else if (cidx == 2) {
                    pred[r0 * 3 + 2] = acc[mt][0] + B4[2];
                    pred[(r0 + 8) * 3 + 2] = acc[mt][2] + B4[2];
                }
            }
        }
    }
    __syncthreads();

    // ---- combine: 32 points per CTA ----------------------------------------
    if (tid < 32) {
        const float* PR = (const float*)(smem + SM_PRED);
        const float* AR = (const float*)(smem + SM_AREA);
        int base = tid * 4;
        float a0 = AR[base], a1 = AR[base + 1], a2 = AR[base + 2], a3 = AR[base + 3];
        float inv = 1.0f / (a0 + a1 + a2 + a3);
        size_t point = (size_t)blockIdx.x * 32 + tid;
        #pragma unroll
        for (int c = 0; c < 3; c++) {
            float v = PR[(base + 0) * 3 + c] * a3 + PR[(base + 1) * 3 + c] * a2 +
                      PR[(base + 2) * 3 + c] * a1 + PR[(base + 3) * 3 + c] * a0;
            out[point * 3 + c] = v * inv;
        }
    }
}

// ============================================================================
// Launch
// ============================================================================
extern "C" void kernel_launch(void* const* d_in, const int* in_sizes, int n_in,
                              void* d_out, int out_size) {
    const float* feat  = (const float*)d_in[0];
    const float* coord = (const float*)d_in[1];
    const float* cell  = (const float*)d_in[2];
    const float* w0 = (const float*)d_in[3];
    const float* b0 = (const float*)d_in[4];
    const float* w1 = (const float*)d_in[5];
    const float* b1 = (const float*)d_in[6];
    const float* w2 = (const float*)d_in[7];
    const float* b2 = (const float*)d_in[8];
    const float* w3 = (const float*)d_in[9];
    const float* b3 = (const float*)d_in[10];
    const float* w4 = (const float*)d_in[11];
    const float* b4 = (const float*)d_in[12];
    float* out = (float*)d_out;

    static bool attr_set = false;
    if (!attr_set) {
        cudaFuncSetAttribute(liif_mlp, cudaFuncAttributeMaxDynamicSharedMemorySize, SMEM_BYTES);
        attr_set = true;
    }

    prep_all<<<(FEAT_N + WTOT + 255) / 256, 256>>>(feat, w0, w1, w2, w3, w4);
    liif_mlp<<<8192, 256, SMEM_BYTES>>>(coord, cell, b0, b1, b2, b3, b4, out);
}

// round 7
// speedup vs baseline: 1.3535x; 1.0202x over previous
#include <cuda_runtime.h>
#include <cuda_fp16.h>
#include <cstdint>

// ============================================================================
// Problem constants
// ============================================================================
#define B_   4
#define C_   64
#define H_   128
#define W_   128
#define Q_   65536
#define FEAT_N (B_ * H_ * W_ * C_)              // 1,048,576
#define WTOT   (32768 + 3 * 65536 + 2048)       // 231,424
// rows = 4 branches * B * Q = 1,048,576 ; 128 rows per CTA -> 8192 CTAs

// ============================================================================
// Device scratch (no cudaMalloc allowed)
// ============================================================================
__device__ __align__(16) __half g_featT[(size_t)FEAT_N];   // [B,H,W,C] fp16
__device__ __align__(16) __half g_w0i[256 * 128];  // [n=256][k=128] (real K=68)
__device__ __align__(16) __half g_w1i[256 * 256];  // [n][k]
__device__ __align__(16) __half g_w2i[256 * 256];
__device__ __align__(16) __half g_w3i[256 * 256];
__device__ __align__(16) __half g_w4i[8 * 256];    // [n=8][k=256] (real N=3)

// ============================================================================
// Fused prep kernel
// ============================================================================
__global__ void prep_all(const float* __restrict__ feat,
                         const float* __restrict__ w0, const float* __restrict__ w1,
                         const float* __restrict__ w2, const float* __restrict__ w3,
                         const float* __restrict__ w4) {
    int o = blockIdx.x * blockDim.x + threadIdx.x;
    if (o < FEAT_N) {
        int c  = o & 63;
        int ix = (o >> 6) & 127;
        int iy = (o >> 13) & 127;
        int b  = o >> 20;
        g_featT[o] = __float2half(feat[(((size_t)b * C_ + c) * H_ + iy) * W_ + ix]);
        return;
    }
    int i = o - FEAT_N;
    if (i < 32768) {                        // W0: [256][128], real K=68
        int n = i >> 7, k = i & 127;
        g_w0i[i] = __float2half(k < 68 ? w0[k * 256 + n] : 0.0f);
    } else if (i < 32768 + 3 * 65536) {     // W1..W3: [256][256]
        int j = i - 32768;
        int l = j >> 16; j &= 65535;
        int n = j >> 8, k = j & 255;
        const float* w = (l == 0) ? w1 : ((l == 1) ? w2 : w3);
        __half* d = (l == 0) ? g_w1i : ((l == 1) ? g_w2i : g_w3i);
        d[j] = __float2half(w[k * 256 + n]);
    } else if (i < WTOT) {                  // W4: [8][256], real N=3
        int j = i - 32768 - 3 * 65536;
        int n = j >> 8, k = j & 255;
        g_w4i[j] = __float2half(n < 3 ? w4[k * 3 + n] : 0.0f);
    }
}

// ============================================================================
// PTX wrappers (baseline PTX, valid at compute_103)
// ============================================================================
__device__ __forceinline__ uint32_t smem_u32(const void* p) {
    uint32_t a;
    asm("{ .reg .u64 t; cvta.to.shared.u64 t, %1; cvt.u32.u64 %0, t; }" : "=r"(a) : "l"(p));
    return a;
}
__device__ __forceinline__ void ldsm_x4(uint32_t* r, uint32_t addr) {
    asm volatile("ldmatrix.sync.aligned.m8n8.x4.shared.b16 {%0,%1,%2,%3}, [%4];"
                 : "=r"(r[0]), "=r"(r[1]), "=r"(r[2]), "=r"(r[3]) : "r"(addr));
}
__device__ __forceinline__ void ldsm_x2(uint32_t* r, uint32_t addr) {
    asm volatile("ldmatrix.sync.aligned.m8n8.x2.shared.b16 {%0,%1}, [%2];"
                 : "=r"(r[0]), "=r"(r[1]) : "r"(addr));
}
__device__ __forceinline__ void stsm_x4(uint32_t addr, uint32_t r0, uint32_t r1,
                                        uint32_t r2, uint32_t r3) {
    asm volatile("stmatrix.sync.aligned.m8n8.x4.shared.b16 [%0], {%1,%2,%3,%4};"
                 :: "r"(addr), "r"(r0), "r"(r1), "r"(r2), "r"(r3) : "memory");
}
__device__ __forceinline__ void mma16816(float* d, const uint32_t* a, const uint32_t* b) {
    asm volatile("mma.sync.aligned.m16n8k16.row.col.f32.f16.f16.f32 "
                 "{%0,%1,%2,%3}, {%4,%5,%6,%7}, {%8,%9}, {%0,%1,%2,%3};"
                 : "+f"(d[0]), "+f"(d[1]), "+f"(d[2]), "+f"(d[3])
                 : "r"(a[0]), "r"(a[1]), "r"(a[2]), "r"(a[3]), "r"(b[0]), "r"(b[1]));
}
__device__ __forceinline__ void cp16(uint32_t dst, const void* src) {
    asm volatile("cp.async.cg.shared.global [%0], [%1], 16;" :: "r"(dst), "l"(src));
}
__device__ __forceinline__ void cp_commit() {
    asm volatile("cp.async.commit_group;" ::: "memory");
}
template <int N> __device__ __forceinline__ void cp_wait() {
    asm volatile("cp.async.wait_group %0;" :: "n"(N) : "memory");
}
__device__ __forceinline__ void barn(int id, int cnt) {
    asm volatile("bar.sync %0, %1;" :: "r"(id), "r"(cnt) : "memory");
}

// ============================================================================
// SMEM layout (dynamic)
// ============================================================================
// act    : [0, 64K)          128 rows x 256 halves (512B/row, swizzled)
// bslice : [64K, 192K)       4 x 32KB pair-private weight slices (64 n x 512B)
// w4     : [192K, 196K)      8 rows x 512B
// bias/b4/area/pred tail
#define SM_ACT   0
#define SM_BSL   65536
#define SM_W4    196608
#define SM_BIAS  200704
#define SM_B4    204800
#define SM_AREA  204816
#define SM_PRED  205328
#define SMEM_BYTES 206864

// chunk = 16B group of 8 halves; swizzle: chunk' = chunk ^ (row & 7)
__device__ __forceinline__ uint32_t swz(int row, int chunk, int rowshift) {
    return ((uint32_t)row << rowshift) + (uint32_t)((chunk ^ (row & 7)) << 4);
}

// ============================================================================
// Full-layer compute: warp tile 64 rows x 64 cols, K = KT*16
// acc in 128 regs; outputs packed fp16 at the end.
// ============================================================================
template <int KT>
__device__ __forceinline__ void compute_full(
    uint32_t act, uint32_t bslice, const float* bias, int wm, int lane,
    uint32_t (&o01)[4][8], uint32_t (&o23)[4][8])
{
    float acc[4][8][4];
    #pragma unroll
    for (int mt = 0; mt < 4; mt++)
        #pragma unroll
        for (int nt = 0; nt < 8; nt++)
            #pragma unroll
            for (int u = 0; u < 4; u++) acc[mt][nt][u] = 0.0f;

    uint32_t a[2][4][4];
    uint32_t bf[2][8][2];

    auto ldf = [&](int kt, int s) {
        #pragma unroll
        for (int mt = 0; mt < 4; mt++)
            ldsm_x4(a[s][mt], act + swz(wm * 64 + mt * 16 + (lane & 15), kt * 2 + (lane >> 4), 9));
        #pragma unroll
        for (int bt = 0; bt < 4; bt++) {
            uint32_t r4[4];
            ldsm_x4(r4, bslice + swz(bt * 16 + (lane & 7) + ((lane >> 4) << 3),
                                     kt * 2 + ((lane >> 3) & 1), 9));
            bf[s][2 * bt][0] = r4[0]; bf[s][2 * bt][1] = r4[1];
            bf[s][2 * bt + 1][0] = r4[2]; bf[s][2 * bt + 1][1] = r4[3];
        }
    };

    ldf(0, 0);
    #pragma unroll
    for (int kt = 0; kt < KT; kt++) {
        const int cur = kt & 1;
        if (kt + 1 < KT) ldf(kt + 1, cur ^ 1);
        #pragma unroll
        for (int mt = 0; mt < 4; mt++)
            #pragma unroll
            for (int nt = 0; nt < 8; nt++)
                mma16816(acc[mt][nt], a[cur][mt], bf[cur][nt]);
    }

    // bias + ReLU + fp16 pack
    #pragma unroll
    for (int mt = 0; mt < 4; mt++)
        #pragma unroll
        for (int nt = 0; nt < 8; nt++) {
            float bb0 = bias[nt * 8 + (lane & 3) * 2];
            float bb1 = bias[nt * 8 + (lane & 3) * 2 + 1];
            float v0 = fmaxf(acc[mt][nt][0] + bb0, 0.0f);
            float v1 = fmaxf(acc[mt][nt][1] + bb1, 0.0f);
            float v2 = fmaxf(acc[mt][nt][2] + bb0, 0.0f);
            float v3 = fmaxf(acc[mt][nt][3] + bb1, 0.0f);
            __half2 p01 = __floats2half2_rn(v0, v1);
            __half2 p23 = __floats2half2_rn(v2, v3);
            o01[mt][nt] = *(uint32_t*)&p01;
            o23[mt][nt] = *(uint32_t*)&p23;
        }
}

// ============================================================================
// Fused MLP kernel: 128 rows/CTA, 8 warps = wm2 x wn4, warp tile 64x64.
// Full-layer passes; pair-private B slices; named-barrier sync only.
// ============================================================================
__global__ void __launch_bounds__(256, 1) liif_mlp(
    const float* __restrict__ coord, const float* __restrict__ cell,
    const float* __restrict__ b0, const float* __restrict__ b1,
    const float* __restrict__ b2, const float* __restrict__ b3,
    const float* __restrict__ b4, float* __restrict__ out)
{
    extern __shared__ char smem[];
    uint32_t sb = smem_u32(smem);
    const int tid = threadIdx.x;
    const int lane = tid & 31;
    const int wid = tid >> 5;
    const int wm = wid >> 2;       // 2 row groups x 64 rows
    const int wn = wid & 3;        // 4 col groups x 64 cols
    const uint32_t bslice = sb + SM_BSL + (uint32_t)wn * 32768;

    // ---- per-pair weight slice load for layer l (warp-scope, k-half split) --
    auto issue_bload = [&](int l) {
        if (l == 0) {
            #pragma unroll 4
            for (int idx = lane; idx < 512; idx += 32) {   // 64 n x 8 chunks
                int n = idx >> 3, c = wm * 8 + (idx & 7);
                cp16(bslice + (uint32_t)n * 512 + (uint32_t)((c ^ (n & 7)) << 4),
                     g_w0i + (size_t)(wn * 64 + n) * 128 + c * 8);
            }
        } else {
            const __half* wsrc = (l == 1) ? g_w1i : (l == 2) ? g_w2i : g_w3i;
            #pragma unroll 4
            for (int idx = lane; idx < 1024; idx += 32) {  // 64 n x 16 chunks
                int n = idx >> 4, c = wm * 16 + (idx & 15);
                cp16(bslice + (uint32_t)n * 512 + (uint32_t)((c ^ (n & 7)) << 4),
                     wsrc + (size_t)(wn * 64 + n) * 256 + c * 8);
            }
        }
        cp_commit();
    };

    // ---- prologue: W0 slices + W4 + biases + gather ------------------------
    issue_bload(0);
    {   // W4: 8 rows x 32 chunks, one per thread
        int n = tid >> 5, c = tid & 31;
        cp16(sb + SM_W4 + (uint32_t)n * 512 + (uint32_t)((c ^ (n & 7)) << 4),
             g_w4i + (size_t)n * 256 + c * 8);
        cp_commit();
    }
    for (int i = tid; i < 1024; i += 256) {
        int l = i >> 8, n = i & 255;
        const float* p = (l == 0) ? b0 : (l == 1) ? b1 : (l == 2) ? b2 : b3;
        *(float*)(smem + SM_BIAS + i * 4) = p[n];
    }
    if (tid < 3) *(float*)(smem + SM_B4 + tid * 4) = b4[tid];

    {
        int i = tid >> 1;                 // local row 0..127
        int part = tid & 1;
        int r = blockIdx.x * 128 + i;     // global row
        int point = r >> 2, j = r & 3;
        int b = point >> 16, q = point & 65535;
        float c0 = coord[(size_t)(b * Q_ + q) * 2 + 0];
        float c1 = coord[(size_t)(b * Q_ + q) * 2 + 1];
        float rc0 = cell[(size_t)(b * Q_ + q) * 2 + 0] * 128.0f;
        float rc1 = cell[(size_t)(b * Q_ + q) * 2 + 1] * 128.0f;
        const float EPS = 1e-6f, RX = 0.0078125f;
        float sx = ((j & 2) ? RX : -RX) + EPS;
        float sy = ((j & 1) ? RX : -RX) + EPS;
        float lo = -1.0f + EPS, hi = 1.0f - EPS;
        float cs0 = fminf(fmaxf(c0 + sx, lo), hi);
        float cs1 = fminf(fmaxf(c1 + sy, lo), hi);
        int iy = (int)fminf(fmaxf(floorf((cs0 + 1.0f) * 64.0f), 0.0f), 127.0f);
        int ix = (int)fminf(fmaxf(floorf((cs1 + 1.0f) * 64.0f), 0.0f), 127.0f);
        float qc0 = (float)(2 * iy + 1) * 0.0078125f - 1.0f;
        float qc1 = (float)(2 * ix + 1) * 0.0078125f - 1.0f;
        float rel0 = (c0 - qc0) * 128.0f;
        float rel1 = (c1 - qc1) * 128.0f;
        if (part == 0)
            *(float*)(smem + SM_AREA + i * 4) = fabsf(rel0 * rel1) + 1e-9f;

        const uint4* fp = (const uint4*)(g_featT + ((size_t)((b << 14) + (iy << 7) + ix) << 6));
        #pragma unroll
        for (int u = 0; u < 4; u++) {
            int ch = part * 4 + u;
            *(uint4*)(smem + SM_ACT + swz(i, ch, 9)) = fp[ch];
        }
        if (part == 1) {
            __half2 h0 = __floats2half2_rn(rel0, rel1);
            __half2 h1 = __floats2half2_rn(rc0, rc1);
            uint4 v;
            v.x = *(uint32_t*)&h0; v.y = *(uint32_t*)&h1; v.z = 0; v.w = 0;
            *(uint4*)(smem + SM_ACT + swz(i, 8, 9)) = v;
            uint4 z; z.x = z.y = z.z = z.w = 0;
            *(uint4*)(smem + SM_ACT + swz(i, 9, 9)) = z;
        }
    }

    cp_wait<0>();
    __syncthreads();

    const uint32_t act = sb + SM_ACT;
    const int g = lane >> 3, lr = lane & 7;
    const int GRP = 1 + wm;        // named barrier ids: 1,2 (128 thr)
    const int PAIR = 4 + wn;       // 4..7 (64 thr)

    uint32_t o01[4][8], o23[4][8];

    // ---- layers 0..3: one full-layer pass each -----------------------------
    #pragma unroll 1
    for (int l = 0; l < 4; l++) {
        const float* biasl = (const float*)(smem + SM_BIAS) + l * 256 + wn * 64;

        if (l == 0)
            compute_full<5>(act, bslice, biasl, wm, lane, o01, o23);
        else
            compute_full<16>(act, bslice, biasl, wm, lane, o01, o23);

        barn(PAIR, 64);                  // pair done reading B slice
        if (l < 3) issue_bload(l + 1);   // refill our slice for next layer
        barn(GRP, 128);                  // wm-group done reading act rows

        // stmatrix outputs into act (rows wm*64..+64, cols wn*64..+64)
        #pragma unroll
        for (int mt = 0; mt < 4; mt++)
            #pragma unroll
            for (int np = 0; np < 4; np++) {
                int row = wm * 64 + mt * 16 + ((g & 1) << 3) + lr;
                int chunk = wn * 8 + np * 2 + (g >> 1);
                stsm_x4(act + swz(row, chunk, 9),
                        o01[mt][2 * np], o23[mt][2 * np],
                        o01[mt][2 * np + 1], o23[mt][2 * np + 1]);
            }

        cp_wait<0>();                    // my k-half of next B slice arrived
        barn(GRP, 128);                  // stores visible to wm-group readers
        barn(PAIR, 64);                  // partner's k-half arrived too
    }

    // ---- final layer: N=8 (real 3), K=256, weights in W4 area --------------
    __syncthreads();                     // cross-group act visibility for L4
    {
        const uint32_t wBase = sb + SM_W4;
        if (wid < 4) {
            float acc[2][4];
            #pragma unroll
            for (int mt = 0; mt < 2; mt++)
                #pragma unroll
                for (int u = 0; u < 4; u++) acc[mt][u] = 0.0f;
            const int arw = wid * 32 + (lane & 15);
            const int brw = lane & 7;
            uint32_t a0[2][4], bf0[2], a1[2][4], bf1[2];
            auto ldf = [&](int kt, uint32_t a[][4], uint32_t* bf) {
                #pragma unroll
                for (int mt = 0; mt < 2; mt++)
                    ldsm_x4(a[mt], act + swz(arw + mt * 16, kt * 2 + (lane >> 4), 9));
                ldsm_x2(bf, wBase + swz(brw, kt * 2 + ((lane >> 3) & 1), 9));
            };
            ldf(0, a0, bf0);
            #pragma unroll
            for (int kt = 0; kt < 16; kt += 2) {
                if (kt + 1 < 16) ldf(kt + 1, a1, bf1);
                #pragma unroll
                for (int mt = 0; mt < 2; mt++) mma16816(acc[mt], a0[mt], bf0);
                if (kt + 2 < 16) ldf(kt + 2, a0, bf0);
                #pragma unroll
                for (int mt = 0; mt < 2; mt++) mma16816(acc[mt], a1[mt], bf1);
            }
            float* pred = (float*)(smem + SM_PRED);
            float* B4 = (float*)(smem + SM_B4);
            #pragma unroll
            for (int mt = 0; mt < 2; mt++) {
                int r0 = wid * 32 + mt * 16 + (lane >> 2);
                int cidx = (lane & 3) * 2;
                if (cidx == 0) {
                    pred[r0 * 3 + 0] = acc[mt][0] + B4[0];
                    pred[r0 * 3 + 1] = acc[mt][1] + B4[1];
                    pred[(r0 + 8) * 3 + 0] = acc[mt][2] + B4[0];
                    pred[(r0 + 8) * 3 + 1] = acc[mt][3] + B4[1];
                } else if (cidx == 2) {
                    pred[r0 * 3 + 2] = acc[mt][0] + B4[2];
                    pred[(r0 + 8) * 3 + 2] = acc[mt][2] + B4[2];
                }
            }
        }
    }
    __syncthreads();

    // ---- combine: 32 points per CTA ----------------------------------------
    if (tid < 32) {
        const float* PR = (const float*)(smem + SM_PRED);
        const float* AR = (const float*)(smem + SM_AREA);
        int base = tid * 4;
        float a0 = AR[base], a1 = AR[base + 1], a2 = AR[base + 2], a3 = AR[base + 3];
        float inv = 1.0f / (a0 + a1 + a2 + a3);
        size_t point = (size_t)blockIdx.x * 32 + tid;
        #pragma unroll
        for (int c = 0; c < 3; c++) {
            float v = PR[(base + 0) * 3 + c] * a3 + PR[(base + 1) * 3 + c] * a2 +
                      PR[(base + 2) * 3 + c] * a1 + PR[(base + 3) * 3 + c] * a0;
            out[point * 3 + c] = v * inv;
        }
    }
}

// ============================================================================
// Launch
// ============================================================================
extern "C" void kernel_launch(void* const* d_in, const int* in_sizes, int n_in,
                              void* d_out, int out_size) {
    const float* feat  = (const float*)d_in[0];
    const float* coord = (const float*)d_in[1];
    const float* cell  = (const float*)d_in[2];
    const float* w0 = (const float*)d_in[3];
    const float* b0 = (const float*)d_in[4];
    const float* w1 = (const float*)d_in[5];
    const float* b1 = (const float*)d_in[6];
    const float* w2 = (const float*)d_in[7];
    const float* b2 = (const float*)d_in[8];
    const float* w3 = (const float*)d_in[9];
    const float* b3 = (const float*)d_in[10];
    const float* w4 = (const float*)d_in[11];
    const float* b4 = (const float*)d_in[12];
    float* out = (float*)d_out;

    static bool attr_set = false;
    if (!attr_set) {
        cudaFuncSetAttribute(liif_mlp, cudaFuncAttributeMaxDynamicSharedMemorySize, SMEM_BYTES);
        attr_set = true;
    }

    prep_all<<<(FEAT_N + WTOT + 255) / 256, 256>>>(feat, w0, w1, w2, w3, w4);
    liif_mlp<<<8192, 256, SMEM_BYTES>>>(coord, cell, b0, b1, b2, b3, b4, out);
}

// round 8
// speedup vs baseline: 1.4252x; 1.0530x over previous
#include <cuda_runtime.h>
#include <cuda_fp16.h>
#include <cstdint>

// ============================================================================
// Problem constants
// ============================================================================
#define B_   4
#define C_   64
#define H_   128
#define W_   128
#define Q_   65536
#define FEAT_N (B_ * H_ * W_ * C_)              // 1,048,576
#define WTOT   (32768 + 3 * 65536 + 2048)       // 231,424
#define NT   8192                               // 128-row tiles total

// ============================================================================
// Device scratch (no cudaMalloc allowed)
// ============================================================================
__device__ __align__(16) __half g_featT[(size_t)FEAT_N];   // [B,H,W,C] fp16
__device__ __align__(16) __half g_w0i[256 * 128];  // [n=256][k=128] (real K=68)
__device__ __align__(16) __half g_w1i[256 * 256];  // [n][k]
__device__ __align__(16) __half g_w2i[256 * 256];
__device__ __align__(16) __half g_w3i[256 * 256];
__device__ __align__(16) __half g_w4i[8 * 256];    // [n=8][k=256] (real N=3)

// ============================================================================
// Fused prep kernel
// ============================================================================
__global__ void prep_all(const float* __restrict__ feat,
                         const float* __restrict__ w0, const float* __restrict__ w1,
                         const float* __restrict__ w2, const float* __restrict__ w3,
                         const float* __restrict__ w4) {
    int o = blockIdx.x * blockDim.x + threadIdx.x;
    if (o < FEAT_N) {
        int c  = o & 63;
        int ix = (o >> 6) & 127;
        int iy = (o >> 13) & 127;
        int b  = o >> 20;
        g_featT[o] = __float2half(feat[(((size_t)b * C_ + c) * H_ + iy) * W_ + ix]);
        return;
    }
    int i = o - FEAT_N;
    if (i < 32768) {                        // W0: [256][128], real K=68
        int n = i >> 7, k = i & 127;
        g_w0i[i] = __float2half(k < 68 ? w0[k * 256 + n] : 0.0f);
    } else if (i < 32768 + 3 * 65536) {     // W1..W3: [256][256]
        int j = i - 32768;
        int l = j >> 16; j &= 65535;
        int n = j >> 8, k = j & 255;
        const float* w = (l == 0) ? w1 : ((l == 1) ? w2 : w3);
        __half* d = (l == 0) ? g_w1i : ((l == 1) ? g_w2i : g_w3i);
        d[j] = __float2half(w[k * 256 + n]);
    } else if (i < WTOT) {                  // W4: [8][256], real N=3
        int j = i - 32768 - 3 * 65536;
        int n = j >> 8, k = j & 255;
        g_w4i[j] = __float2half(n < 3 ? w4[k * 3 + n] : 0.0f);
    }
}

// ============================================================================
// PTX wrappers (baseline PTX, valid at compute_103)
// ============================================================================
__device__ __forceinline__ uint32_t smem_u32(const void* p) {
    uint32_t a;
    asm("{ .reg .u64 t; cvta.to.shared.u64 t, %1; cvt.u32.u64 %0, t; }" : "=r"(a) : "l"(p));
    return a;
}
__device__ __forceinline__ void ldsm_x4(uint32_t* r, uint32_t addr) {
    asm volatile("ldmatrix.sync.aligned.m8n8.x4.shared.b16 {%0,%1,%2,%3}, [%4];"
                 : "=r"(r[0]), "=r"(r[1]), "=r"(r[2]), "=r"(r[3]) : "r"(addr));
}
__device__ __forceinline__ void ldsm_x2(uint32_t* r, uint32_t addr) {
    asm volatile("ldmatrix.sync.aligned.m8n8.x2.shared.b16 {%0,%1}, [%2];"
                 : "=r"(r[0]), "=r"(r[1]) : "r"(addr));
}
__device__ __forceinline__ void stsm_x4(uint32_t addr, uint32_t r0, uint32_t r1,
                                        uint32_t r2, uint32_t r3) {
    asm volatile("stmatrix.sync.aligned.m8n8.x4.shared.b16 [%0], {%1,%2,%3,%4};"
                 :: "r"(addr), "r"(r0), "r"(r1), "r"(r2), "r"(r3) : "memory");
}
__device__ __forceinline__ void mma16816(float* d, const uint32_t* a, const uint32_t* b) {
    asm volatile("mma.sync.aligned.m16n8k16.row.col.f32.f16.f16.f32 "
                 "{%0,%1,%2,%3}, {%4,%5,%6,%7}, {%8,%9}, {%0,%1,%2,%3};"
                 : "+f"(d[0]), "+f"(d[1]), "+f"(d[2]), "+f"(d[3])
                 : "r"(a[0]), "r"(a[1]), "r"(a[2]), "r"(a[3]), "r"(b[0]), "r"(b[1]));
}
__device__ __forceinline__ void cp16(uint32_t dst, const void* src) {
    asm volatile("cp.async.cg.shared.global [%0], [%1], 16;" :: "r"(dst), "l"(src));
}
__device__ __forceinline__ void cp_commit() {
    asm volatile("cp.async.commit_group;" ::: "memory");
}
template <int N> __device__ __forceinline__ void cp_wait() {
    asm volatile("cp.async.wait_group %0;" :: "n"(N) : "memory");
}
__device__ __forceinline__ void barn(int id, int cnt) {
    asm volatile("bar.sync %0, %1;" :: "r"(id), "r"(cnt) : "memory");
}

// ============================================================================
// SMEM layout (dynamic)
// ============================================================================
// act : [0, 64K)            128 rows x 256 halves (512B/row, swizzled)
// P   : [64K, +20480)       input buffer: 128 rows x 160B (K=80, prefetch target)
// bsl : [86016, +128K)      4 x 32KB pair-private weight slices (64 n x 512B)
// w4  : [217088, +4K)       8 rows x 512B
// bias/b4/areaA/areaB/pred tail
#define SM_ACT    0
#define SM_P      65536
#define SM_BSL    86016
#define SM_W4     217088
#define SM_BIAS   221184
#define SM_B4     225280
#define SM_AREAA  225296
#define SM_AREAB  225808
#define SM_PRED   226320
#define SMEM_BYTES 227856

// chunk = 16B group of 8 halves; swizzle: chunk' = chunk ^ (row & 7)
__device__ __forceinline__ uint32_t swz(int row, int chunk, int rowshift) {
    return ((uint32_t)row << rowshift) + (uint32_t)((chunk ^ (row & 7)) << 4);
}
// P-buffer addressing: 160B rows, chunks 0..7 swizzled, 8..9 plain
__device__ __forceinline__ uint32_t addrP(int row, int chunk) {
    int c = (chunk < 8) ? (chunk ^ (row & 7)) : chunk;
    return (uint32_t)row * 160u + ((uint32_t)c << 4);
}

// ============================================================================
// Full-layer compute: warp tile 64 rows x 64 cols, K = KT*16
// ============================================================================
template <int KT, bool FROMP>
__device__ __forceinline__ void compute_full(
    uint32_t abase, uint32_t bslice, const float* bias, int wm, int lane,
    uint32_t (&o01)[4][8], uint32_t (&o23)[4][8])
{
    float acc[4][8][4];
    #pragma unroll
    for (int mt = 0; mt < 4; mt++)
        #pragma unroll
        for (int nt = 0; nt < 8; nt++)
            #pragma unroll
            for (int u = 0; u < 4; u++) acc[mt][nt][u] = 0.0f;

    uint32_t a[2][4][4];
    uint32_t bf[2][8][2];

    auto ldf = [&](int kt, int s) {
        #pragma unroll
        for (int mt = 0; mt < 4; mt++) {
            int row = wm * 64 + mt * 16 + (lane & 15);
            int ch = kt * 2 + (lane >> 4);
            uint32_t ad = FROMP ? (abase + addrP(row, ch))
                                : (abase + swz(row, ch, 9));
            ldsm_x4(a[s][mt], ad);
        }
        #pragma unroll
        for (int bt = 0; bt < 4; bt++) {
            uint32_t r4[4];
            ldsm_x4(r4, bslice + swz(bt * 16 + (lane & 7) + ((lane >> 4) << 3),
                                     kt * 2 + ((lane >> 3) & 1), 9));
            bf[s][2 * bt][0] = r4[0]; bf[s][2 * bt][1] = r4[1];
            bf[s][2 * bt + 1][0] = r4[2]; bf[s][2 * bt + 1][1] = r4[3];
        }
    };

    ldf(0, 0);
    #pragma unroll
    for (int kt = 0; kt < KT; kt++) {
        const int cur = kt & 1;
        if (kt + 1 < KT) ldf(kt + 1, cur ^ 1);
        #pragma unroll
        for (int mt = 0; mt < 4; mt++)
            #pragma unroll
            for (int nt = 0; nt < 8; nt++)
                mma16816(acc[mt][nt], a[cur][mt], bf[cur][nt]);
    }

    #pragma unroll
    for (int mt = 0; mt < 4; mt++)
        #pragma unroll
        for (int nt = 0; nt < 8; nt++) {
            float bb0 = bias[nt * 8 + (lane & 3) * 2];
            float bb1 = bias[nt * 8 + (lane & 3) * 2 + 1];
            float v0 = fmaxf(acc[mt][nt][0] + bb0, 0.0f);
            float v1 = fmaxf(acc[mt][nt][1] + bb1, 0.0f);
            float v2 = fmaxf(acc[mt][nt][2] + bb0, 0.0f);
            float v3 = fmaxf(acc[mt][nt][3] + bb1, 0.0f);
            __half2 p01 = __floats2half2_rn(v0, v1);
            __half2 p23 = __floats2half2_rn(v2, v3);
            o01[mt][nt] = *(uint32_t*)&p01;
            o23[mt][nt] = *(uint32_t*)&p23;
        }
}

// ============================================================================
// Persistent fused MLP kernel: grid = #SMs, each CTA loops over 128-row tiles.
// 8 warps = wm2 x wn4, warp tile 64x64. Gather prefetched one tile ahead.
// ============================================================================
__global__ void __launch_bounds__(256, 1) liif_mlp(
    const float* __restrict__ coord, const float* __restrict__ cell,
    const float* __restrict__ b0, const float* __restrict__ b1,
    const float* __restrict__ b2, const float* __restrict__ b3,
    const float* __restrict__ b4, float* __restrict__ out)
{
    extern __shared__ char smem[];
    uint32_t sb = smem_u32(smem);
    const int tid = threadIdx.x;
    const int lane = tid & 31;
    const int wid = tid >> 5;
    const int wm = wid >> 2;       // 2 row groups x 64 rows
    const int wn = wid & 3;        // 4 col groups x 64 cols
    const uint32_t act = sb + SM_ACT;
    const uint32_t P = sb + SM_P;
    const uint32_t bslice = sb + SM_BSL + (uint32_t)wn * 32768;
    const int g = lane >> 3, lr = lane & 7;
    const int GRP = 1 + wm;        // 128-thread barriers (ids 1,2)
    const int PAIR = 4 + wn;       // 64-thread barriers (ids 4..7)

    // ---- gather prefetch for one tile into P + area buffer (no commit) -----
    auto prefetch_gather = [&](int tile, uint32_t areaOff) {
        int i = tid >> 1, part = tid & 1;
        int r = tile * 128 + i;
        int point = r >> 2, j = r & 3;
        int b = point >> 16, q = point & 65535;
        const float* cp = coord + (size_t)(b * Q_ + q) * 2;
        float c0 = cp[0], c1 = cp[1];
        const float* cl = cell + (size_t)(b * Q_ + q) * 2;
        float rc0 = cl[0] * 128.0f, rc1 = cl[1] * 128.0f;
        const float EPS = 1e-6f, RX = 0.0078125f;
        float sx = ((j & 2) ? RX : -RX) + EPS;
        float sy = ((j & 1) ? RX : -RX) + EPS;
        float lo = -1.0f + EPS, hi = 1.0f - EPS;
        float cs0 = fminf(fmaxf(c0 + sx, lo), hi);
        float cs1 = fminf(fmaxf(c1 + sy, lo), hi);
        int iy = (int)fminf(fmaxf(floorf((cs0 + 1.0f) * 64.0f), 0.0f), 127.0f);
        int ix = (int)fminf(fmaxf(floorf((cs1 + 1.0f) * 64.0f), 0.0f), 127.0f);
        float qc0 = (float)(2 * iy + 1) * 0.0078125f - 1.0f;
        float qc1 = (float)(2 * ix + 1) * 0.0078125f - 1.0f;
        float rel0 = (c0 - qc0) * 128.0f;
        float rel1 = (c1 - qc1) * 128.0f;
        if (part == 0)
            *(float*)(smem + areaOff + i * 4) = fabsf(rel0 * rel1) + 1e-9f;

        const char* fp = (const char*)(g_featT + ((size_t)((b << 14) + (iy << 7) + ix) << 6));
        #pragma unroll
        for (int u = 0; u < 4; u++) {
            int c = part * 4 + u;
            cp16(P + (uint32_t)i * 160u + (uint32_t)((c ^ (i & 7)) << 4), fp + c * 16);
        }
        if (part == 1) {
            __half2 h0 = __floats2half2_rn(rel0, rel1);
            __half2 h1 = __floats2half2_rn(rc0, rc1);
            uint4 v;
            v.x = *(uint32_t*)&h0; v.y = *(uint32_t*)&h1; v.z = 0; v.w = 0;
            *(uint4*)(smem + SM_P + i * 160 + 128) = v;          // chunk 8
            uint4 z; z.x = z.y = z.z = z.w = 0;
            *(uint4*)(smem + SM_P + i * 160 + 144) = z;          // chunk 9
        }
    };

    // ---- per-pair weight slice load for layer l (warp-scope, k-half split) --
    auto issue_bload = [&](int l) {
        if (l == 0) {
            #pragma unroll 4
            for (int idx = lane; idx < 512; idx += 32) {   // 64 n x 8 chunks
                int n = idx >> 3, c = wm * 8 + (idx & 7);
                cp16(bslice + (uint32_t)n * 512 + (uint32_t)((c ^ (n & 7)) << 4),
                     g_w0i + (size_t)(wn * 64 + n) * 128 + c * 8);
            }
        } else {
            const __half* wsrc = (l == 1) ? g_w1i : (l == 2) ? g_w2i : g_w3i;
            #pragma unroll 4
            for (int idx = lane; idx < 1024; idx += 32) {  // 64 n x 16 chunks
                int n = idx >> 4, c = wm * 16 + (idx & 15);
                cp16(bslice + (uint32_t)n * 512 + (uint32_t)((c ^ (n & 7)) << 4),
                     wsrc + (size_t)(wn * 64 + n) * 256 + c * 8);
            }
        }
        cp_commit();
    };

    auto store_out = [&](uint32_t (&o01)[4][8], uint32_t (&o23)[4][8]) {
        #pragma unroll
        for (int mt = 0; mt < 4; mt++)
            #pragma unroll
            for (int np = 0; np < 4; np++) {
                int row = wm * 64 + mt * 16 + ((g & 1) << 3) + lr;
                int chunk = wn * 8 + np * 2 + (g >> 1);
                stsm_x4(act + swz(row, chunk, 9),
                        o01[mt][2 * np], o23[mt][2 * np],
                        o01[mt][2 * np + 1], o23[mt][2 * np + 1]);
            }
    };

    // ---- prologue ----------------------------------------------------------
    prefetch_gather((int)blockIdx.x, SM_AREAA);
    cp_commit();
    {   // W4: 8 rows x 32 chunks, one per thread
        int n = tid >> 5, c = tid & 31;
        cp16(sb + SM_W4 + (uint32_t)n * 512 + (uint32_t)((c ^ (n & 7)) << 4),
             g_w4i + (size_t)n * 256 + c * 8);
        cp_commit();
    }
    issue_bload(0);
    for (int i = tid; i < 1024; i += 256) {
        int l = i >> 8, n = i & 255;
        const float* p = (l == 0) ? b0 : (l == 1) ? b1 : (l == 2) ? b2 : b3;
        *(float*)(smem + SM_BIAS + i * 4) = p[n];
    }
    if (tid < 3) *(float*)(smem + SM_B4 + tid * 4) = b4[tid];
    cp_wait<0>();
    __syncthreads();

    uint32_t areaCur = SM_AREAA, areaNxt = SM_AREAB;
    uint32_t o01[4][8], o23[4][8];
    const float* biasB = (const float*)(smem + SM_BIAS);

    // ---- persistent tile loop ----------------------------------------------
    for (int tile = blockIdx.x; tile < NT; tile += gridDim.x) {
        const int next = tile + gridDim.x;

        // layer 0 (A from P)
        compute_full<5, true>(P, bslice, biasB + wn * 64, wm, lane, o01, o23);
        barn(PAIR, 64);
        issue_bload(1);
        barn(GRP, 128);                // P + act reads done within wm-group
        store_out(o01, o23);
        if (next < NT) prefetch_gather(next, areaNxt);
        cp_commit();                   // prefetch group (possibly empty)
        cp_wait<1>();                  // L1 weights done; prefetch may fly
        barn(GRP, 128); barn(PAIR, 64);

        // layers 1..3
        #pragma unroll 1
        for (int l = 1; l < 4; l++) {
            compute_full<16, false>(act, bslice, biasB + l * 256 + wn * 64, wm, lane, o01, o23);
            barn(PAIR, 64);
            issue_bload((l + 1) & 3);  // l=3 -> reload L0 for next tile
            barn(GRP, 128);
            store_out(o01, o23);
            cp_wait<0>();
            barn(GRP, 128); barn(PAIR, 64);
        }

        // final layer: N=8 (real 3), K=256 — all 8 warps, 16 rows each
        __syncthreads();
        {
            const uint32_t wBase = sb + SM_W4;
            float acc[4];
            #pragma unroll
            for (int u = 0; u < 4; u++) acc[u] = 0.0f;
            const int arw = wid * 16 + (lane & 15);
            const int brw = lane & 7;
            uint32_t a0[4], bf0[2], a1[4], bf1[2];
            auto ldf4 = [&](int kt, uint32_t* a, uint32_t* bf) {
                ldsm_x4(a, act + swz(arw, kt * 2 + (lane >> 4), 9));
                ldsm_x2(bf, wBase + swz(brw, kt * 2 + ((lane >> 3) & 1), 9));
            };
            ldf4(0, a0, bf0);
            #pragma unroll
            for (int kt = 0; kt < 16; kt += 2) {
                if (kt + 1 < 16) ldf4(kt + 1, a1, bf1);
                mma16816(acc, a0, bf0);
                if (kt + 2 < 16) ldf4(kt + 2, a0, bf0);
                mma16816(acc, a1, bf1);
            }
            float* pred = (float*)(smem + SM_PRED);
            float* B4 = (float*)(smem + SM_B4);
            int r0 = wid * 16 + (lane >> 2);
            int cidx = (lane & 3) * 2;
            if (cidx == 0) {
                pred[r0 * 3 + 0] = acc[0] + B4[0];
                pred[r0 * 3 + 1] = acc[1] + B4[1];
                pred[(r0 + 8) * 3 + 0] = acc[2] + B4[0];
                pred[(r0 + 8) * 3 + 1] = acc[3] + B4[1];
            } else if (cidx == 2) {
                pred[r0 * 3 + 2] = acc[0] + B4[2];
                pred[(r0 + 8) * 3 + 2] = acc[2] + B4[2];
            }
        }
        __syncthreads();

        // combine: 32 points
        if (tid < 32) {
            const float* PR = (const float*)(smem + SM_PRED);
            const float* AR = (const float*)(smem + areaCur);
            int base = tid * 4;
            float a0 = AR[base], a1 = AR[base + 1], a2 = AR[base + 2], a3 = AR[base + 3];
            float inv = 1.0f / (a0 + a1 + a2 + a3);
            size_t point = (size_t)tile * 32 + tid;
            #pragma unroll
            for (int c = 0; c < 3; c++) {
                float v = PR[(base + 0) * 3 + c] * a3 + PR[(base + 1) * 3 + c] * a2 +
                          PR[(base + 2) * 3 + c] * a1 + PR[(base + 3) * 3 + c] * a0;
                out[point * 3 + c] = v * inv;
            }
        }
        __syncthreads();               // protect area/pred before next tile reuse

        uint32_t t = areaCur; areaCur = areaNxt; areaNxt = t;
    }
}

// ============================================================================
// Launch
// ============================================================================
extern "C" void kernel_launch(void* const* d_in, const int* in_sizes, int n_in,
                              void* d_out, int out_size) {
    const float* feat  = (const float*)d_in[0];
    const float* coord = (const float*)d_in[1];
    const float* cell  = (const float*)d_in[2];
    const float* w0 = (const float*)d_in[3];
    const float* b0 = (const float*)d_in[4];
    const float* w1 = (const float*)d_in[5];
    const float* b1 = (const float*)d_in[6];
    const float* w2 = (const float*)d_in[7];
    const float* b2 = (const float*)d_in[8];
    const float* w3 = (const float*)d_in[9];
    const float* b3 = (const float*)d_in[10];
    const float* w4 = (const float*)d_in[11];
    const float* b4 = (const float*)d_in[12];
    float* out = (float*)d_out;

    static int nsm = 0;
    if (nsm == 0) {
        cudaFuncSetAttribute(liif_mlp, cudaFuncAttributeMaxDynamicSharedMemorySize, SMEM_BYTES);
        int dev = 0;
        cudaGetDevice(&dev);
        cudaDeviceGetAttribute(&nsm, cudaDevAttrMultiProcessorCount, dev);
        if (nsm <= 0) nsm = 148;
    }

    prep_all<<<(FEAT_N + WTOT + 255) / 256, 256>>>(feat, w0, w1, w2, w3, w4);
    liif_mlp<<<nsm, 256, SMEM_BYTES>>>(coord, cell, b0, b1, b2, b3, b4, out);
}

// round 9
// speedup vs baseline: 1.4286x; 1.0024x over previous
#include <cuda_runtime.h>
#include <cuda_fp16.h>
#include <cstdint>

// ============================================================================
// Problem constants
// ============================================================================
#define B_   4
#define C_   64
#define H_   128
#define W_   128
#define Q_   65536
#define FEAT_N (B_ * H_ * W_ * C_)              // 1,048,576
#define WTOT   (32768 + 3 * 65536 + 2048)       // 231,424
#define NT   8192                               // 128-row tiles total

// ============================================================================
// Device scratch (no cudaMalloc allowed)
// ============================================================================
__device__ __align__(16) __half g_featT[(size_t)FEAT_N];   // [B,H,W,C] fp16
__device__ __align__(16) __half g_w0i[256 * 128];  // [n=256][k=128] (real K=68)
__device__ __align__(16) __half g_w1i[256 * 256];  // [n][k]
__device__ __align__(16) __half g_w2i[256 * 256];
__device__ __align__(16) __half g_w3i[256 * 256];
__device__ __align__(16) __half g_w4i[8 * 256];    // [n=8][k=256] (real N=3)

// ============================================================================
// Fused prep kernel
// ============================================================================
__global__ void prep_all(const float* __restrict__ feat,
                         const float* __restrict__ w0, const float* __restrict__ w1,
                         const float* __restrict__ w2, const float* __restrict__ w3,
                         const float* __restrict__ w4) {
    int o = blockIdx.x * blockDim.x + threadIdx.x;
    if (o < FEAT_N) {
        int c  = o & 63;
        int ix = (o >> 6) & 127;
        int iy = (o >> 13) & 127;
        int b  = o >> 20;
        g_featT[o] = __float2half(feat[(((size_t)b * C_ + c) * H_ + iy) * W_ + ix]);
        return;
    }
    int i = o - FEAT_N;
    if (i < 32768) {                        // W0: [256][128], real K=68
        int n = i >> 7, k = i & 127;
        g_w0i[i] = __float2half(k < 68 ? w0[k * 256 + n] : 0.0f);
    } else if (i < 32768 + 3 * 65536) {     // W1..W3: [256][256]
        int j = i - 32768;
        int l = j >> 16; j &= 65535;
        int n = j >> 8, k = j & 255;
        const float* w = (l == 0) ? w1 : ((l == 1) ? w2 : w3);
        __half* d = (l == 0) ? g_w1i : ((l == 1) ? g_w2i : g_w3i);
        d[j] = __float2half(w[k * 256 + n]);
    } else if (i < WTOT) {                  // W4: [8][256], real N=3
        int j = i - 32768 - 3 * 65536;
        int n = j >> 8, k = j & 255;
        g_w4i[j] = __float2half(n < 3 ? w4[k * 3 + n] : 0.0f);
    }
}

// ============================================================================
// PTX wrappers (baseline PTX, valid at compute_103)
// ============================================================================
__device__ __forceinline__ uint32_t smem_u32(const void* p) {
    uint32_t a;
    asm("{ .reg .u64 t; cvta.to.shared.u64 t, %1; cvt.u32.u64 %0, t; }" : "=r"(a) : "l"(p));
    return a;
}
__device__ __forceinline__ void ldsm_x4(uint32_t* r, uint32_t addr) {
    asm volatile("ldmatrix.sync.aligned.m8n8.x4.shared.b16 {%0,%1,%2,%3}, [%4];"
                 : "=r"(r[0]), "=r"(r[1]), "=r"(r[2]), "=r"(r[3]) : "r"(addr));
}
__device__ __forceinline__ void ldsm_x2(uint32_t* r, uint32_t addr) {
    asm volatile("ldmatrix.sync.aligned.m8n8.x2.shared.b16 {%0,%1}, [%2];"
                 : "=r"(r[0]), "=r"(r[1]) : "r"(addr));
}
__device__ __forceinline__ void stsm_x4(uint32_t addr, uint32_t r0, uint32_t r1,
                                        uint32_t r2, uint32_t r3) {
    asm volatile("stmatrix.sync.aligned.m8n8.x4.shared.b16 [%0], {%1,%2,%3,%4};"
                 :: "r"(addr), "r"(r0), "r"(r1), "r"(r2), "r"(r3) : "memory");
}
__device__ __forceinline__ void mma16816(float* d, const uint32_t* a, const uint32_t* b) {
    asm volatile("mma.sync.aligned.m16n8k16.row.col.f32.f16.f16.f32 "
                 "{%0,%1,%2,%3}, {%4,%5,%6,%7}, {%8,%9}, {%0,%1,%2,%3};"
                 : "+f"(d[0]), "+f"(d[1]), "+f"(d[2]), "+f"(d[3])
                 : "r"(a[0]), "r"(a[1]), "r"(a[2]), "r"(a[3]), "r"(b[0]), "r"(b[1]));
}
__device__ __forceinline__ void cp16(uint32_t dst, const void* src) {
    asm volatile("cp.async.cg.shared.global [%0], [%1], 16;" :: "r"(dst), "l"(src));
}
__device__ __forceinline__ void cp_commit() {
    asm volatile("cp.async.commit_group;" ::: "memory");
}
template <int N> __device__ __forceinline__ void cp_wait() {
    asm volatile("cp.async.wait_group %0;" :: "n"(N) : "memory");
}
__device__ __forceinline__ void barn(int id, int cnt) {
    asm volatile("bar.sync %0, %1;" :: "r"(id), "r"(cnt) : "memory");
}

// ============================================================================
// SMEM layout (dynamic)
// ============================================================================
#define SM_ACT    0
#define SM_P      65536
#define SM_BSL    86016
#define SM_W4     217088
#define SM_BIAS   221184
#define SM_B4     225280
#define SM_AREAA  225296
#define SM_AREAB  225808
#define SM_PRED   226320
#define SMEM_BYTES 227856

// chunk = 16B group of 8 halves; swizzle: chunk' = chunk ^ (row & 7)
__device__ __forceinline__ uint32_t swz(int row, int chunk, int rowshift) {
    return ((uint32_t)row << rowshift) + (uint32_t)((chunk ^ (row & 7)) << 4);
}
// P-buffer addressing: 160B rows, chunks 0..7 swizzled, 8..9 plain
__device__ __forceinline__ uint32_t addrP(int row, int chunk) {
    int c = (chunk < 8) ? (chunk ^ (row & 7)) : chunk;
    return (uint32_t)row * 160u + ((uint32_t)c << 4);
}

// ============================================================================
// Full-layer compute: warp tile 64 rows x 64 cols, K = KT*16
// ============================================================================
template <int KT, bool FROMP>
__device__ __forceinline__ void compute_full(
    uint32_t abase, uint32_t bslice, const float* bias, int wm, int lane,
    uint32_t (&o01)[4][8], uint32_t (&o23)[4][8])
{
    float acc[4][8][4];
    #pragma unroll
    for (int mt = 0; mt < 4; mt++)
        #pragma unroll
        for (int nt = 0; nt < 8; nt++)
            #pragma unroll
            for (int u = 0; u < 4; u++) acc[mt][nt][u] = 0.0f;

    uint32_t a[2][4][4];
    uint32_t bf[2][8][2];

    auto ldf = [&](int kt, int s) {
        #pragma unroll
        for (int mt = 0; mt < 4; mt++) {
            int row = wm * 64 + mt * 16 + (lane & 15);
            int ch = kt * 2 + (lane >> 4);
            uint32_t ad = FROMP ? (abase + addrP(row, ch))
                                : (abase + swz(row, ch, 9));
            ldsm_x4(a[s][mt], ad);
        }
        #pragma unroll
        for (int bt = 0; bt < 4; bt++) {
            uint32_t r4[4];
            ldsm_x4(r4, bslice + swz(bt * 16 + (lane & 7) + ((lane >> 4) << 3),
                                     kt * 2 + ((lane >> 3) & 1), 9));
            bf[s][2 * bt][0] = r4[0]; bf[s][2 * bt][1] = r4[1];
            bf[s][2 * bt + 1][0] = r4[2]; bf[s][2 * bt + 1][1] = r4[3];
        }
    };

    ldf(0, 0);
    #pragma unroll
    for (int kt = 0; kt < KT; kt++) {
        const int cur = kt & 1;
        if (kt + 1 < KT) ldf(kt + 1, cur ^ 1);
        #pragma unroll
        for (int mt = 0; mt < 4; mt++)
            #pragma unroll
            for (int nt = 0; nt < 8; nt++)
                mma16816(acc[mt][nt], a[cur][mt], bf[cur][nt]);
    }

    #pragma unroll
    for (int mt = 0; mt < 4; mt++)
        #pragma unroll
        for (int nt = 0; nt < 8; nt++) {
            float bb0 = bias[nt * 8 + (lane & 3) * 2];
            float bb1 = bias[nt * 8 + (lane & 3) * 2 + 1];
            float v0 = fmaxf(acc[mt][nt][0] + bb0, 0.0f);
            float v1 = fmaxf(acc[mt][nt][1] + bb1, 0.0f);
            float v2 = fmaxf(acc[mt][nt][2] + bb0, 0.0f);
            float v3 = fmaxf(acc[mt][nt][3] + bb1, 0.0f);
            __half2 p01 = __floats2half2_rn(v0, v1);
            __half2 p23 = __floats2half2_rn(v2, v3);
            o01[mt][nt] = *(uint32_t*)&p01;
            o23[mt][nt] = *(uint32_t*)&p23;
        }
}

// ============================================================================
// Persistent fused MLP kernel: grid = #SMs, tile loop inside.
// 8 warps = wm2 x wn4, warp tile 64x64. L4 computed from L3 registers
// (D-fragment == A-fragment reuse) + smem atomic reduction over wn.
// ============================================================================
__global__ void __launch_bounds__(256, 1) liif_mlp(
    const float* __restrict__ coord, const float* __restrict__ cell,
    const float* __restrict__ b0, const float* __restrict__ b1,
    const float* __restrict__ b2, const float* __restrict__ b3,
    const float* __restrict__ b4, float* __restrict__ out)
{
    extern __shared__ char smem[];
    uint32_t sb = smem_u32(smem);
    const int tid = threadIdx.x;
    const int lane = tid & 31;
    const int wid = tid >> 5;
    const int wm = wid >> 2;       // 2 row groups x 64 rows
    const int wn = wid & 3;        // 4 col groups x 64 cols
    const uint32_t act = sb + SM_ACT;
    const uint32_t P = sb + SM_P;
    const uint32_t bslice = sb + SM_BSL + (uint32_t)wn * 32768;
    const int g = lane >> 3, lr = lane & 7;
    const int GRP = 1 + wm;        // 128-thread barriers (ids 1,2)
    const int PAIR = 4 + wn;       // 64-thread barriers (ids 4..7)

    // ---- gather prefetch for one tile into P + area buffer (no commit) -----
    auto prefetch_gather = [&](int tile, uint32_t areaOff) {
        int i = tid >> 1, part = tid & 1;
        int r = tile * 128 + i;
        int point = r >> 2, j = r & 3;
        int b = point >> 16, q = point & 65535;
        const float* cp = coord + (size_t)(b * Q_ + q) * 2;
        float c0 = cp[0], c1 = cp[1];
        const float* cl = cell + (size_t)(b * Q_ + q) * 2;
        float rc0 = cl[0] * 128.0f, rc1 = cl[1] * 128.0f;
        const float EPS = 1e-6f, RX = 0.0078125f;
        float sx = ((j & 2) ? RX : -RX) + EPS;
        float sy = ((j & 1) ? RX : -RX) + EPS;
        float lo = -1.0f + EPS, hi = 1.0f - EPS;
        float cs0 = fminf(fmaxf(c0 + sx, lo), hi);
        float cs1 = fminf(fmaxf(c1 + sy, lo), hi);
        int iy = (int)fminf(fmaxf(floorf((cs0 + 1.0f) * 64.0f), 0.0f), 127.0f);
        int ix = (int)fminf(fmaxf(floorf((cs1 + 1.0f) * 64.0f), 0.0f), 127.0f);
        float qc0 = (float)(2 * iy + 1) * 0.0078125f - 1.0f;
        float qc1 = (float)(2 * ix + 1) * 0.0078125f - 1.0f;
        float rel0 = (c0 - qc0) * 128.0f;
        float rel1 = (c1 - qc1) * 128.0f;
        if (part == 0)
            *(float*)(smem + areaOff + i * 4) = fabsf(rel0 * rel1) + 1e-9f;

        const char* fp = (const char*)(g_featT + ((size_t)((b << 14) + (iy << 7) + ix) << 6));
        #pragma unroll
        for (int u = 0; u < 4; u++) {
            int c = part * 4 + u;
            cp16(P + (uint32_t)i * 160u + (uint32_t)((c ^ (i & 7)) << 4), fp + c * 16);
        }
        if (part == 1) {
            __half2 h0 = __floats2half2_rn(rel0, rel1);
            __half2 h1 = __floats2half2_rn(rc0, rc1);
            uint4 v;
            v.x = *(uint32_t*)&h0; v.y = *(uint32_t*)&h1; v.z = 0; v.w = 0;
            *(uint4*)(smem + SM_P + i * 160 + 128) = v;          // chunk 8
        }
    };

    // ---- per-pair weight slice load for layer l (warp-scope, k-half split) --
    auto issue_bload = [&](int l) {
        if (l == 0) {
            #pragma unroll 4
            for (int idx = lane; idx < 512; idx += 32) {   // 64 n x 8 chunks
                int n = idx >> 3, c = wm * 8 + (idx & 7);
                cp16(bslice + (uint32_t)n * 512 + (uint32_t)((c ^ (n & 7)) << 4),
                     g_w0i + (size_t)(wn * 64 + n) * 128 + c * 8);
            }
        } else {
            const __half* wsrc = (l == 1) ? g_w1i : (l == 2) ? g_w2i : g_w3i;
            #pragma unroll 4
            for (int idx = lane; idx < 1024; idx += 32) {  // 64 n x 16 chunks
                int n = idx >> 4, c = wm * 16 + (idx & 15);
                cp16(bslice + (uint32_t)n * 512 + (uint32_t)((c ^ (n & 7)) << 4),
                     wsrc + (size_t)(wn * 64 + n) * 256 + c * 8);
            }
        }
        cp_commit();
    };

    auto store_out = [&](uint32_t (&o01)[4][8], uint32_t (&o23)[4][8]) {
        #pragma unroll
        for (int mt = 0; mt < 4; mt++)
            #pragma unroll
            for (int np = 0; np < 4; np++) {
                int row = wm * 64 + mt * 16 + ((g & 1) << 3) + lr;
                int chunk = wn * 8 + np * 2 + (g >> 1);
                stsm_x4(act + swz(row, chunk, 9),
                        o01[mt][2 * np], o23[mt][2 * np],
                        o01[mt][2 * np + 1], o23[mt][2 * np + 1]);
            }
    };

    // ---- prologue ----------------------------------------------------------
    prefetch_gather((int)blockIdx.x, SM_AREAA);
    cp_commit();
    {   // W4: 8 rows x 32 chunks, one per thread
        int n = tid >> 5, c = tid & 31;
        cp16(sb + SM_W4 + (uint32_t)n * 512 + (uint32_t)((c ^ (n & 7)) << 4),
             g_w4i + (size_t)n * 256 + c * 8);
        cp_commit();
    }
    issue_bload(0);
    for (int i = tid; i < 1024; i += 256) {
        int l = i >> 8, n = i & 255;
        const float* p = (l == 0) ? b0 : (l == 1) ? b1 : (l == 2) ? b2 : b3;
        *(float*)(smem + SM_BIAS + i * 4) = p[n];
    }
    if (tid < 3) *(float*)(smem + SM_B4 + tid * 4) = b4[tid];
    // P chunk 9 (constant zero padding) — written once
    if (tid < 128) {
        uint4 z; z.x = z.y = z.z = z.w = 0;
        *(uint4*)(smem + SM_P + tid * 160 + 144) = z;
    }
    // zero pred
    for (int i = tid; i < 384; i += 256) ((float*)(smem + SM_PRED))[i] = 0.0f;
    cp_wait<0>();
    __syncthreads();

    uint32_t areaCur = SM_AREAA, areaNxt = SM_AREAB;
    uint32_t o01[4][8], o23[4][8];
    const float* biasB = (const float*)(smem + SM_BIAS);

    // ---- persistent tile loop ----------------------------------------------
    for (int tile = blockIdx.x; tile < NT; tile += gridDim.x) {
        const int next = tile + gridDim.x;

        // layer 0 (A from P)
        compute_full<5, true>(P, bslice, biasB + wn * 64, wm, lane, o01, o23);
        barn(PAIR, 64);
        issue_bload(1);
        barn(GRP, 128);                // P + act reads done within wm-group
        store_out(o01, o23);
        if (next < NT) prefetch_gather(next, areaNxt);
        cp_commit();                   // prefetch group (possibly empty)
        cp_wait<1>();                  // L1 weights done; prefetch may fly
        barn(GRP, 128); barn(PAIR, 64);

        // layers 1..2
        #pragma unroll 1
        for (int l = 1; l < 3; l++) {
            compute_full<16, false>(act, bslice, biasB + l * 256 + wn * 64, wm, lane, o01, o23);
            barn(PAIR, 64);
            issue_bload(l + 1);
            barn(GRP, 128);
            store_out(o01, o23);
            cp_wait<0>();
            barn(GRP, 128); barn(PAIR, 64);
        }

        // layer 3: compute, keep outputs in registers (no act store)
        compute_full<16, false>(act, bslice, biasB + 3 * 256 + wn * 64, wm, lane, o01, o23);
        barn(PAIR, 64);
        issue_bload(0);                // refill W0 slice for next tile

        // layer 4 from registers: D-frag == A-frag; B from W4 at k = wn*64..
        {
            float a4[4][4];
            #pragma unroll
            for (int mt = 0; mt < 4; mt++)
                #pragma unroll
                for (int u = 0; u < 4; u++) a4[mt][u] = 0.0f;
            uint32_t bfr[4][2];
            #pragma unroll
            for (int j = 0; j < 4; j++)
                ldsm_x2(bfr[j], sb + SM_W4 + swz(lane & 7, (wn * 4 + j) * 2 + ((lane >> 3) & 1), 9));
            #pragma unroll
            for (int mt = 0; mt < 4; mt++)
                #pragma unroll
                for (int j = 0; j < 4; j++) {
                    uint32_t afr[4] = { o01[mt][2 * j], o23[mt][2 * j],
                                        o01[mt][2 * j + 1], o23[mt][2 * j + 1] };
                    mma16816(a4[mt], afr, bfr[j]);
                }
            // reduce partials over wn via smem atomics (cols 0..2 real)
            float* pred = (float*)(smem + SM_PRED);
            int t4 = lane & 3, g2 = lane >> 2;
            if (t4 == 0) {
                #pragma unroll
                for (int mt = 0; mt < 4; mt++) {
                    int r = wm * 64 + mt * 16 + g2;
                    atomicAdd(&pred[r * 3 + 0], a4[mt][0]);
                    atomicAdd(&pred[r * 3 + 1], a4[mt][1]);
                    atomicAdd(&pred[(r + 8) * 3 + 0], a4[mt][2]);
                    atomicAdd(&pred[(r + 8) * 3 + 1], a4[mt][3]);
                }
            } else if (t4 == 1) {
                #pragma unroll
                for (int mt = 0; mt < 4; mt++) {
                    int r = wm * 64 + mt * 16 + g2;
                    atomicAdd(&pred[r * 3 + 2], a4[mt][0]);
                    atomicAdd(&pred[(r + 8) * 3 + 2], a4[mt][2]);
                }
            }
        }
        __syncthreads();

        // combine: 32 points (b4 folded in: ensemble weights sum to 1)
        if (tid < 32) {
            const float* PR = (const float*)(smem + SM_PRED);
            const float* AR = (const float*)(smem + areaCur);
            const float* B4 = (const float*)(smem + SM_B4);
            int base = tid * 4;
            float a0 = AR[base], a1 = AR[base + 1], a2 = AR[base + 2], a3 = AR[base + 3];
            float inv = 1.0f / (a0 + a1 + a2 + a3);
            size_t point = (size_t)tile * 32 + tid;
            #pragma unroll
            for (int c = 0; c < 3; c++) {
                float v = PR[(base + 0) * 3 + c] * a3 + PR[(base + 1) * 3 + c] * a2 +
                          PR[(base + 2) * 3 + c] * a1 + PR[(base + 3) * 3 + c] * a0;
                out[point * 3 + c] = v * inv + B4[c];
            }
        }
        __syncthreads();

        // zero own group's pred rows (visibility to next tile's atomics via GRP)
        {
            float* pred = (float*)(smem + SM_PRED);
            int i = tid & 127;
            int base = wm * 192;                 // 64 rows * 3
            pred[base + i] = 0.0f;
            if (i < 64) pred[base + 128 + i] = 0.0f;
        }
        cp_wait<0>();                  // W0 slice (and stragglers) arrived
        barn(PAIR, 64);                // both k-halves visible to pair

        uint32_t t = areaCur; areaCur = areaNxt; areaNxt = t;
    }
}

// ============================================================================
// Launch
// ============================================================================
extern "C" void kernel_launch(void* const* d_in, const int* in_sizes, int n_in,
                              void* d_out, int out_size) {
    const float* feat  = (const float*)d_in[0];
    const float* coord = (const float*)d_in[1];
    const float* cell  = (const float*)d_in[2];
    const float* w0 = (const float*)d_in[3];
    const float* b0 = (const float*)d_in[4];
    const float* w1 = (const float*)d_in[5];
    const float* b1 = (const float*)d_in[6];
    const float* w2 = (const float*)d_in[7];
    const float* b2 = (const float*)d_in[8];
    const float* w3 = (const float*)d_in[9];
    const float* b3 = (const float*)d_in[10];
    const float* w4 = (const float*)d_in[11];
    const float* b4 = (const float*)d_in[12];
    float* out = (float*)d_out;

    static int nsm = 0;
    if (nsm == 0) {
        cudaFuncSetAttribute(liif_mlp, cudaFuncAttributeMaxDynamicSharedMemorySize, SMEM_BYTES);
        int dev = 0;
        cudaGetDevice(&dev);
        cudaDeviceGetAttribute(&nsm, cudaDevAttrMultiProcessorCount, dev);
        if (nsm <= 0) nsm = 148;
    }

    prep_all<<<(FEAT_N + WTOT + 255) / 256, 256>>>(feat, w0, w1, w2, w3, w4);
    liif_mlp<<<nsm, 256, SMEM_BYTES>>>(coord, cell, b0, b1, b2, b3, b4, out);
}